// round 4
// baseline (speedup 1.0000x reference)
#include <cuda_runtime.h>
#include <cstdint>
#include <math.h>

#define Bx     256
#define Tx     128
#define ENCX   1024
#define UX     1024
#define EMBX   512
#define VOCABX 32000
#define XDIM   1536
#define WXN    3072
#define GXN    2048
#define SMSTRIDE 136   // 128 + 8 pad -> conflict-free tf32 fragment LDS
#define NKT    32      // K tiles of 32 over K=1024

// ---------------- scratch ----------------
__device__ float g_hw2[Bx * UX];
__device__ float g_S[Bx * Tx];
__device__ float g_attn[Bx * Tx];
__device__ float g_xt[Bx * XDIM];
__device__ float g_gx[Bx * GXN];
__device__ float g_W1t[UX * ENCX];   // W1 transposed (N,K), tf32-rounded

__device__ __forceinline__ float f2tf(float f) {
    unsigned u;
    asm("cvt.rna.tf32.f32 %0, %1;" : "=r"(u) : "f"(f));
    return __uint_as_float(u);
}

__device__ __forceinline__ void mma_tf32(float* c, const unsigned* a, const unsigned* b) {
    asm volatile(
        "mma.sync.aligned.m16n8k8.row.col.f32.tf32.tf32.f32 "
        "{%0,%1,%2,%3}, {%4,%5,%6,%7}, {%8,%9}, {%0,%1,%2,%3};"
        : "+f"(c[0]), "+f"(c[1]), "+f"(c[2]), "+f"(c[3])
        : "r"(a[0]), "r"(a[1]), "r"(a[2]), "r"(a[3]), "r"(b[0]), "r"(b[1]));
}

// ---------------- zero S ----------------
__global__ void k_zero_S() {
    int i = blockIdx.x * blockDim.x + threadIdx.x;
    if (i < Bx * Tx) g_S[i] = 0.f;
}

// ---------------- transpose W1 -> g_W1t (N,K), tf32-rounded ----------------
__global__ void k_transpose_W1(const float* __restrict__ W1) {
    __shared__ float t[32][33];
    int bx = blockIdx.x * 32, by = blockIdx.y * 32;
    int x = threadIdx.x, y0 = threadIdx.y;
#pragma unroll
    for (int i = 0; i < 32; i += 8)
        t[y0 + i][x] = W1[(size_t)(by + y0 + i) * UX + bx + x];
    __syncthreads();
#pragma unroll
    for (int i = 0; i < 32; i += 8)
        g_W1t[(size_t)(bx + y0 + i) * ENCX + by + x] = f2tf(t[x][y0 + i]);
}

// ---------------- hw2 = hidden @ W2 + (b1 + b2) ----------------
__global__ void k_hw2(const float* __restrict__ hidden, const float* __restrict__ W2,
                      const float* __restrict__ b1, const float* __restrict__ b2) {
    __shared__ float As[16][64];
    __shared__ float Bs[16][64];
    int tid = threadIdx.x;
    int m0 = blockIdx.y * 64, n0 = blockIdx.x * 64;
    int ar = tid >> 2, ac = (tid & 3) << 2;
    int br = tid >> 4, bc = (tid & 15) << 2;
    int ty = tid >> 4, tx = tid & 15;
    float acc[4][4] = {};
    for (int k0 = 0; k0 < UX; k0 += 16) {
        float4 av = *(const float4*)&hidden[(size_t)(m0 + ar) * UX + k0 + ac];
        float4 bv = *(const float4*)&W2[(size_t)(k0 + br) * UX + n0 + bc];
        __syncthreads();
        As[ac + 0][ar] = av.x; As[ac + 1][ar] = av.y;
        As[ac + 2][ar] = av.z; As[ac + 3][ar] = av.w;
        *(float4*)&Bs[br][bc] = bv;
        __syncthreads();
#pragma unroll
        for (int k = 0; k < 16; k++) {
            float ra[4], rb[4];
#pragma unroll
            for (int i = 0; i < 4; i++) ra[i] = As[k][ty * 4 + i];
#pragma unroll
            for (int j = 0; j < 4; j++) rb[j] = Bs[k][tx * 4 + j];
#pragma unroll
            for (int i = 0; i < 4; i++)
#pragma unroll
                for (int j = 0; j < 4; j++) acc[i][j] += ra[i] * rb[j];
        }
    }
#pragma unroll
    for (int i = 0; i < 4; i++) {
        int m = m0 + ty * 4 + i;
#pragma unroll
        for (int j = 0; j < 4; j++) {
            int n = n0 + tx * 4 + j;
            g_hw2[(size_t)m * UX + n] = acc[i][j] + b1[n] + b2[n];
        }
    }
}

// ================= score GEMM (mma.sync tf32, reg-staged double buffer) ======
// M = B*T (BM=128 == one batch b), N = U, K = ENC. BM=128, BN=128, BK=32.
// 8 warps 2(m) x 4(n); warptile 64x32. Fused epilogue tanh(acc+hw2)*V -> S.
// grid (8, 256). Dynamic smem:
//   As: 2 x 32 x SMSTRIDE floats @ 0      (34816 B)
//   Bs: 2 x 32 x SMSTRIDE floats @ 34816  (34816 B)
//   hw2s[128] @ 69632, Vs[128] @ 70144, red[128][5] @ 70656. total 73216 B.
#define SC_BS_OFF  (2 * 32 * SMSTRIDE)
#define SC_HW2_OFF (4 * 32 * SMSTRIDE)
#define SC_VS_OFF  (SC_HW2_OFF + 128)
#define SC_RED_OFF (SC_VS_OFF + 128)
#define SC_SMEM_BYTES ((SC_RED_OFF + 128 * 5) * 4)

__global__ void __launch_bounds__(256, 1)
k_score_tc(const float* __restrict__ enc, const float* __restrict__ V) {
    extern __shared__ float sm[];
    float* AsBase = sm;
    float* BsBase = sm + SC_BS_OFF;
    float* hw2s   = sm + SC_HW2_OFF;
    float* Vs     = sm + SC_VS_OFF;
    float* red    = sm + SC_RED_OFF;

    int tid = threadIdx.x;
    int lane = tid & 31, wid = tid >> 5;
    int warp_m = wid & 1, warp_n = wid >> 1;
    int g = lane >> 2, tig = lane & 3;
    int b = blockIdx.y;
    int n0 = blockIdx.x * 128;

    if (tid < 128) {
        hw2s[tid] = g_hw2[(size_t)b * UX + n0 + tid];
        Vs[tid] = V[n0 + tid];
    }

    // load mapping: 1024 float4 per tile, 4 per thread
    int arow = (tid * 4) >> 3 >> 2;              // not used; explicit below
    const float* encB = enc + (size_t)b * Tx * ENCX;
    const float* W1tB = g_W1t + (size_t)n0 * ENCX;

    float4 ar[4], br[4];
    int arw[4], acc4[4], brw[4], bcc4[4];
#pragma unroll
    for (int i = 0; i < 4; i++) {
        int idx = i * 256 + tid;
        arw[i] = idx >> 3; acc4[i] = idx & 7;    // row 0..127, float4-col 0..7
        brw[i] = idx >> 3; bcc4[i] = idx & 7;
    }

#define SC_LOAD(J) do { \
    int k0 = (J) * 32; \
    _Pragma("unroll") \
    for (int i = 0; i < 4; i++) { \
        ar[i] = *(const float4*)(encB + (size_t)arw[i] * ENCX + k0 + acc4[i] * 4); \
        br[i] = *(const float4*)(W1tB + (size_t)brw[i] * ENCX + k0 + bcc4[i] * 4); \
    } } while (0)

#define SC_STORE(BUF) do { \
    float* Asb = AsBase + (BUF) * 32 * SMSTRIDE; \
    float* Bsb = BsBase + (BUF) * 32 * SMSTRIDE; \
    _Pragma("unroll") \
    for (int i = 0; i < 4; i++) { \
        int ka = acc4[i] * 4, ma = arw[i]; \
        Asb[(ka + 0) * SMSTRIDE + ma] = f2tf(ar[i].x); \
        Asb[(ka + 1) * SMSTRIDE + ma] = f2tf(ar[i].y); \
        Asb[(ka + 2) * SMSTRIDE + ma] = f2tf(ar[i].z); \
        Asb[(ka + 3) * SMSTRIDE + ma] = f2tf(ar[i].w); \
        int kb = bcc4[i] * 4, nb = brw[i]; \
        Bsb[(kb + 0) * SMSTRIDE + nb] = br[i].x; \
        Bsb[(kb + 1) * SMSTRIDE + nb] = br[i].y; \
        Bsb[(kb + 2) * SMSTRIDE + nb] = br[i].z; \
        Bsb[(kb + 3) * SMSTRIDE + nb] = br[i].w; \
    } } while (0)

    float acc[4][4][4] = {};

    SC_LOAD(0);
    SC_STORE(0);
    SC_LOAD(1);
    __syncthreads();

    for (int j = 0; j < NKT; j++) {
        int cur = j & 1;
        if (j + 1 < NKT) SC_STORE(cur ^ 1);
        if (j + 2 < NKT) SC_LOAD(j + 2);
        float* Asb = AsBase + cur * 32 * SMSTRIDE;
        float* Bsb = BsBase + cur * 32 * SMSTRIDE;
#pragma unroll
        for (int kk = 0; kk < 32; kk += 8) {
            unsigned afr[4][4], bfr[4][2];
#pragma unroll
            for (int i = 0; i < 4; i++) {
                int row = warp_m * 64 + i * 16 + g;
                afr[i][0] = __float_as_uint(Asb[(kk + tig) * SMSTRIDE + row]);
                afr[i][1] = __float_as_uint(Asb[(kk + tig) * SMSTRIDE + row + 8]);
                afr[i][2] = __float_as_uint(Asb[(kk + tig + 4) * SMSTRIDE + row]);
                afr[i][3] = __float_as_uint(Asb[(kk + tig + 4) * SMSTRIDE + row + 8]);
            }
#pragma unroll
            for (int jn = 0; jn < 4; jn++) {
                int col = warp_n * 32 + jn * 8 + g;
                bfr[jn][0] = __float_as_uint(Bsb[(kk + tig) * SMSTRIDE + col]);
                bfr[jn][1] = __float_as_uint(Bsb[(kk + tig + 4) * SMSTRIDE + col]);
            }
#pragma unroll
            for (int i = 0; i < 4; i++)
#pragma unroll
                for (int jn = 0; jn < 4; jn++) mma_tf32(acc[i][jn], afr[i], bfr[jn]);
        }
        __syncthreads();
    }

    // epilogue: per-row sum of tanh(acc + hw2)*V
#pragma unroll
    for (int i = 0; i < 4; i++) {
        float s0 = 0.f, s1 = 0.f;
#pragma unroll
        for (int jn = 0; jn < 4; jn++) {
            int nb = warp_n * 32 + jn * 8 + tig * 2;
#pragma unroll
            for (int c = 0; c < 2; c++) {
                int n = nb + c;
                s0 += tanhf(acc[i][jn][c] + hw2s[n]) * Vs[n];
                s1 += tanhf(acc[i][jn][2 + c] + hw2s[n]) * Vs[n];
            }
        }
        s0 += __shfl_xor_sync(0xffffffffu, s0, 1);
        s0 += __shfl_xor_sync(0xffffffffu, s0, 2);
        s1 += __shfl_xor_sync(0xffffffffu, s1, 1);
        s1 += __shfl_xor_sync(0xffffffffu, s1, 2);
        if (tig == 0) {
            int r0 = warp_m * 64 + i * 16 + g;
            red[r0 * 5 + warp_n] = s0;
            red[(r0 + 8) * 5 + warp_n] = s1;
        }
    }
    __syncthreads();
    if (tid < 128) {
        float s = red[tid * 5 + 0] + red[tid * 5 + 1] + red[tid * 5 + 2] + red[tid * 5 + 3];
        atomicAdd(&g_S[b * Tx + tid], s);
    }
}

// ---------------- softmax over T + emb gather ----------------
__global__ void k_softmax(const int* __restrict__ x, const float* __restrict__ E,
                          float* __restrict__ attn_out) {
    int b = blockIdx.x;
    int tid = threadIdx.x;
    __shared__ float sh[128];
    float s = g_S[b * Tx + tid];
    sh[tid] = s;
    __syncthreads();
    for (int off = 64; off; off >>= 1) {
        if (tid < off) sh[tid] = fmaxf(sh[tid], sh[tid + off]);
        __syncthreads();
    }
    float mx = sh[0];
    __syncthreads();
    float e = expf(s - mx);
    sh[tid] = e;
    __syncthreads();
    for (int off = 64; off; off >>= 1) {
        if (tid < off) sh[tid] = sh[tid] + sh[tid + off];
        __syncthreads();
    }
    float a = e / sh[0];
    g_attn[b * Tx + tid] = a;
    attn_out[b * Tx + tid] = a;
    int row = x[b];
    for (int e2 = tid; e2 < EMBX; e2 += 128)
        g_xt[(size_t)b * XDIM + ENCX + e2] = E[(size_t)row * EMBX + e2];
}

// ---------------- context ----------------
__global__ void k_ctx(const float* __restrict__ enc) {
    int b = blockIdx.x;
    int ec = blockIdx.y * 256 + threadIdx.x;
    __shared__ float attn_sh[128];
    if (threadIdx.x < 128) attn_sh[threadIdx.x] = g_attn[b * Tx + threadIdx.x];
    __syncthreads();
    const float* p = enc + (size_t)b * Tx * ENCX + ec;
    float c = 0.f;
#pragma unroll 8
    for (int t = 0; t < Tx; t++) c += attn_sh[t] * p[(size_t)t * ENCX];
    g_xt[(size_t)b * XDIM + ec] = c;
}

// ---------------- gates ----------------
__global__ void k_gate(const float* __restrict__ Wx, const float* __restrict__ bg) {
    __shared__ float As[16][64];
    __shared__ float Bs[16][64];
    int tid = threadIdx.x;
    int m0 = blockIdx.y * 64;
    int nv0 = blockIdx.x * 64;
    int na0 = (nv0 < UX) ? nv0 : nv0 + UX;
    int ar = tid >> 2, ac = (tid & 3) << 2;
    int br = tid >> 4, bc = (tid & 15) << 2;
    int ty = tid >> 4, tx = tid & 15;
    float acc[4][4] = {};
    for (int k0 = 0; k0 < XDIM; k0 += 16) {
        float4 av = *(const float4*)&g_xt[(size_t)(m0 + ar) * XDIM + k0 + ac];
        float4 bv = *(const float4*)&Wx[(size_t)(k0 + br) * WXN + na0 + bc];
        __syncthreads();
        As[ac + 0][ar] = av.x; As[ac + 1][ar] = av.y;
        As[ac + 2][ar] = av.z; As[ac + 3][ar] = av.w;
        *(float4*)&Bs[br][bc] = bv;
        __syncthreads();
#pragma unroll
        for (int k = 0; k < 16; k++) {
            float ra[4], rb[4];
#pragma unroll
            for (int i = 0; i < 4; i++) ra[i] = As[k][ty * 4 + i];
#pragma unroll
            for (int j = 0; j < 4; j++) rb[j] = Bs[k][tx * 4 + j];
#pragma unroll
            for (int i = 0; i < 4; i++)
#pragma unroll
                for (int j = 0; j < 4; j++) acc[i][j] += ra[i] * rb[j];
        }
    }
#pragma unroll
    for (int i = 0; i < 4; i++) {
        int m = m0 + ty * 4 + i;
#pragma unroll
        for (int j = 0; j < 4; j++) {
            int nv = nv0 + tx * 4 + j;
            int na = na0 + tx * 4 + j;
            g_gx[(size_t)m * GXN + nv] = acc[i][j] + bg[na];
        }
    }
}

// ---------------- state ----------------
__global__ void k_state(float* __restrict__ out_state) {
    int i = blockIdx.x * blockDim.x + threadIdx.x;
    if (i >= Bx * UX) return;
    int bb = i >> 10, u = i & 1023;
    float gz = g_gx[(size_t)bb * GXN + u];
    float gh = g_gx[(size_t)bb * GXN + UX + u];
    float z = 1.f / (1.f + expf(-gz));
    out_state[i] = (1.f - z) * tanhf(gh);
}

// ============ logits GEMM (mma.sync tf32, reg-staged double buffer) ==========
// M=256, N=32000, K=1024. BM=128, BN=128, BK=32. grid (250, 2).
// Dynamic smem: As 2x32xSMSTRIDE @0, Bs @34816. 69632 B.
#define LG_BS_OFF (2 * 32 * SMSTRIDE)
#define LG_SMEM_BYTES (4 * 32 * SMSTRIDE * 4)

__global__ void __launch_bounds__(256, 1)
k_logits_tc(const float* __restrict__ A, const float* __restrict__ Wfc,
            const float* __restrict__ bfc, float* __restrict__ C) {
    extern __shared__ float sm[];
    float* AsBase = sm;
    float* BsBase = sm + LG_BS_OFF;

    int tid = threadIdx.x;
    int lane = tid & 31, wid = tid >> 5;
    int warp_m = wid & 1, warp_n = wid >> 1;
    int g = lane >> 2, tig = lane & 3;
    int m0 = blockIdx.y * 128, n0 = blockIdx.x * 128;

    // A: 128 m x 32 k, K-major float4: idx>>3 = m, idx&7 = k4
    // B: 32 k x 128 n, N-major float4: idx>>5 = k, idx&31 = n4
    float4 ar[4], br[4];
    int am[4], ak4[4], bk[4], bn4[4];
#pragma unroll
    for (int i = 0; i < 4; i++) {
        int idx = i * 256 + tid;
        am[i] = idx >> 3; ak4[i] = idx & 7;
        bk[i] = idx >> 5; bn4[i] = idx & 31;
    }
    const float* Ab = A + (size_t)m0 * UX;
    const float* Bb = Wfc + n0;

#define LG_LOAD(J) do { \
    int k0 = (J) * 32; \
    _Pragma("unroll") \
    for (int i = 0; i < 4; i++) { \
        ar[i] = *(const float4*)(Ab + (size_t)am[i] * UX + k0 + ak4[i] * 4); \
        br[i] = *(const float4*)(Bb + (size_t)(k0 + bk[i]) * VOCABX + bn4[i] * 4); \
    } } while (0)

#define LG_STORE(BUF) do { \
    float* Asb = AsBase + (BUF) * 32 * SMSTRIDE; \
    float* Bsb = BsBase + (BUF) * 32 * SMSTRIDE; \
    _Pragma("unroll") \
    for (int i = 0; i < 4; i++) { \
        int ka = ak4[i] * 4, ma = am[i]; \
        Asb[(ka + 0) * SMSTRIDE + ma] = f2tf(ar[i].x); \
        Asb[(ka + 1) * SMSTRIDE + ma] = f2tf(ar[i].y); \
        Asb[(ka + 2) * SMSTRIDE + ma] = f2tf(ar[i].z); \
        Asb[(ka + 3) * SMSTRIDE + ma] = f2tf(ar[i].w); \
        float4 bt; \
        bt.x = f2tf(br[i].x); bt.y = f2tf(br[i].y); \
        bt.z = f2tf(br[i].z); bt.w = f2tf(br[i].w); \
        *(float4*)&Bsb[bk[i] * SMSTRIDE + bn4[i] * 4] = bt; \
    } } while (0)

    float acc[4][4][4] = {};

    LG_LOAD(0);
    LG_STORE(0);
    LG_LOAD(1);
    __syncthreads();

    for (int j = 0; j < NKT; j++) {
        int cur = j & 1;
        if (j + 1 < NKT) LG_STORE(cur ^ 1);
        if (j + 2 < NKT) LG_LOAD(j + 2);
        float* Asb = AsBase + cur * 32 * SMSTRIDE;
        float* Bsb = BsBase + cur * 32 * SMSTRIDE;
#pragma unroll
        for (int kk = 0; kk < 32; kk += 8) {
            unsigned afr[4][4], bfr[4][2];
#pragma unroll
            for (int i = 0; i < 4; i++) {
                int row = warp_m * 64 + i * 16 + g;
                afr[i][0] = __float_as_uint(Asb[(kk + tig) * SMSTRIDE + row]);
                afr[i][1] = __float_as_uint(Asb[(kk + tig) * SMSTRIDE + row + 8]);
                afr[i][2] = __float_as_uint(Asb[(kk + tig + 4) * SMSTRIDE + row]);
                afr[i][3] = __float_as_uint(Asb[(kk + tig + 4) * SMSTRIDE + row + 8]);
            }
#pragma unroll
            for (int jn = 0; jn < 4; jn++) {
                int col = warp_n * 32 + jn * 8 + g;
                bfr[jn][0] = __float_as_uint(Bsb[(kk + tig) * SMSTRIDE + col]);
                bfr[jn][1] = __float_as_uint(Bsb[(kk + tig + 4) * SMSTRIDE + col]);
            }
#pragma unroll
            for (int i = 0; i < 4; i++)
#pragma unroll
                for (int jn = 0; jn < 4; jn++) mma_tf32(acc[i][jn], afr[i], bfr[jn]);
        }
        __syncthreads();
    }

#pragma unroll
    for (int i = 0; i < 4; i++) {
        int r = m0 + warp_m * 64 + i * 16 + g;
#pragma unroll
        for (int jn = 0; jn < 4; jn++) {
            int n = n0 + warp_n * 32 + jn * 8 + tig * 2;
            float bf0 = bfc[n], bf1 = bfc[n + 1];
            *(float2*)&C[(size_t)r * VOCABX + n] =
                make_float2(acc[i][jn][0] + bf0, acc[i][jn][1] + bf1);
            *(float2*)&C[(size_t)(r + 8) * VOCABX + n] =
                make_float2(acc[i][jn][2] + bf0, acc[i][jn][3] + bf1);
        }
    }
}

// ---------------- launcher ----------------
extern "C" void kernel_launch(void* const* d_in, const int* in_sizes, int n_in,
                              void* d_out, int out_size) {
    const int*   x      = (const int*)d_in[0];
    const float* hidden = (const float*)d_in[1];
    const float* enc    = (const float*)d_in[2];
    const float* E      = (const float*)d_in[3];
    const float* W1     = (const float*)d_in[4];
    const float* b1     = (const float*)d_in[5];
    const float* W2     = (const float*)d_in[6];
    const float* b2     = (const float*)d_in[7];
    const float* V      = (const float*)d_in[8];
    const float* Wx     = (const float*)d_in[10];
    const float* b_gru  = (const float*)d_in[12];
    const float* Wfc    = (const float*)d_in[13];
    const float* bfc    = (const float*)d_in[14];

    float* out        = (float*)d_out;
    float* out_logits = out;
    float* out_state  = out + (size_t)Bx * VOCABX;
    float* out_attn   = out + (size_t)Bx * VOCABX + Bx * UX;

    cudaFuncSetAttribute(k_score_tc, cudaFuncAttributeMaxDynamicSharedMemorySize,
                         SC_SMEM_BYTES);
    cudaFuncSetAttribute(k_logits_tc, cudaFuncAttributeMaxDynamicSharedMemorySize,
                         LG_SMEM_BYTES);

    k_zero_S<<<(Bx * Tx + 255) / 256, 256>>>();
    k_transpose_W1<<<dim3(32, 32), dim3(32, 8)>>>(W1);
    k_hw2<<<dim3(UX / 64, Bx / 64), 256>>>(hidden, W2, b1, b2);
    k_score_tc<<<dim3(UX / 128, Bx), 256, SC_SMEM_BYTES>>>(enc, V);
    k_softmax<<<Bx, 128>>>(x, E, out_attn);
    k_ctx<<<dim3(Bx, ENCX / 256), 256>>>(enc);
    k_gate<<<dim3(GXN / 64, Bx / 64), 256>>>(Wx, b_gru);
    k_state<<<(Bx * UX + 255) / 256, 256>>>(out_state);
    k_logits_tc<<<dim3(VOCABX / 128, Bx / 128), 256, LG_SMEM_BYTES>>>(
        out_state, Wfc, bfc, out_logits);
}

// round 5
// speedup vs baseline: 1.6464x; 1.6464x over previous
#include <cuda_runtime.h>
#include <cstdint>
#include <math.h>

#define Bx     256
#define Tx     128
#define ENCX   1024
#define UX     1024
#define EMBX   512
#define VOCABX 32000
#define XDIM   1536
#define WXN    3072
#define GXN    2048
#define NKT    32          // K tiles of 32 over K=1024
#define ASTRIDE 36         // 32 + 4 pad; 144B rows (16B-aligned, conflict-free frags)
#define BSTRIDE 136        // logits B tile: 128 + 8 pad; 544B rows

// ---------------- scratch ----------------
__device__ float g_hw2[Bx * UX];
__device__ float g_S[Bx * Tx];
__device__ float g_attn[Bx * Tx];
__device__ float g_xt[Bx * XDIM];
__device__ float g_gx[Bx * GXN];
__device__ float g_statet[Bx * UX];       // tf32-rounded state
__device__ float g_W1t[UX * ENCX];        // W1 transposed (N,K), tf32-rounded
__device__ float g_enct[Bx * Tx * ENCX];  // enc, tf32-rounded (134MB)

__device__ __forceinline__ float f2tf(float f) {
    unsigned u;
    asm("cvt.rna.tf32.f32 %0, %1;" : "=r"(u) : "f"(f));
    return __uint_as_float(u);
}
__device__ __forceinline__ uint32_t smem_to_u32(const void* p) {
    uint32_t a;
    asm("{ .reg .u64 t; cvta.to.shared.u64 t, %1; cvt.u32.u64 %0, t; }"
        : "=r"(a) : "l"(p));
    return a;
}
__device__ __forceinline__ void cp_async16(uint32_t s, const void* g) {
    asm volatile("cp.async.ca.shared.global [%0], [%1], 16;" :: "r"(s), "l"(g));
}
#define CP_COMMIT() asm volatile("cp.async.commit_group;")
#define CP_WAIT0()  asm volatile("cp.async.wait_group 0;")

__device__ __forceinline__ void mma_tf32(float* c, const unsigned* a, const unsigned* b) {
    asm volatile(
        "mma.sync.aligned.m16n8k8.row.col.f32.tf32.tf32.f32 "
        "{%0,%1,%2,%3}, {%4,%5,%6,%7}, {%8,%9}, {%0,%1,%2,%3};"
        : "+f"(c[0]), "+f"(c[1]), "+f"(c[2]), "+f"(c[3])
        : "r"(a[0]), "r"(a[1]), "r"(a[2]), "r"(a[3]), "r"(b[0]), "r"(b[1]));
}

// ---------------- zero S ----------------
__global__ void k_zero_S() {
    int i = blockIdx.x * blockDim.x + threadIdx.x;
    if (i < Bx * Tx) g_S[i] = 0.f;
}

// ---------------- round enc -> g_enct (tf32 RNA) ----------------
__global__ void k_round_enc(const float* __restrict__ enc) {
    size_t i = (size_t)(blockIdx.x * blockDim.x + threadIdx.x) * 4;
    size_t n = (size_t)Bx * Tx * ENCX;
    if (i >= n) return;
    float4 v = *(const float4*)(enc + i);
    v.x = f2tf(v.x); v.y = f2tf(v.y); v.z = f2tf(v.z); v.w = f2tf(v.w);
    *(float4*)(g_enct + i) = v;
}

// ---------------- transpose W1 -> g_W1t (N,K), tf32-rounded ----------------
__global__ void k_transpose_W1(const float* __restrict__ W1) {
    __shared__ float t[32][33];
    int bx = blockIdx.x * 32, by = blockIdx.y * 32;
    int x = threadIdx.x, y0 = threadIdx.y;
#pragma unroll
    for (int i = 0; i < 32; i += 8)
        t[y0 + i][x] = W1[(size_t)(by + y0 + i) * UX + bx + x];
    __syncthreads();
#pragma unroll
    for (int i = 0; i < 32; i += 8)
        g_W1t[(size_t)(bx + y0 + i) * ENCX + by + x] = f2tf(t[x][y0 + i]);
}

// ---------------- hw2 = hidden @ W2 + (b1 + b2) ----------------
__global__ void k_hw2(const float* __restrict__ hidden, const float* __restrict__ W2,
                      const float* __restrict__ b1, const float* __restrict__ b2) {
    __shared__ float As[16][64];
    __shared__ float Bs[16][64];
    int tid = threadIdx.x;
    int m0 = blockIdx.y * 64, n0 = blockIdx.x * 64;
    int ar = tid >> 2, ac = (tid & 3) << 2;
    int br = tid >> 4, bc = (tid & 15) << 2;
    int ty = tid >> 4, tx = tid & 15;
    float acc[4][4] = {};
    for (int k0 = 0; k0 < UX; k0 += 16) {
        float4 av = *(const float4*)&hidden[(size_t)(m0 + ar) * UX + k0 + ac];
        float4 bv = *(const float4*)&W2[(size_t)(k0 + br) * UX + n0 + bc];
        __syncthreads();
        As[ac + 0][ar] = av.x; As[ac + 1][ar] = av.y;
        As[ac + 2][ar] = av.z; As[ac + 3][ar] = av.w;
        *(float4*)&Bs[br][bc] = bv;
        __syncthreads();
#pragma unroll
        for (int k = 0; k < 16; k++) {
            float ra[4], rb[4];
#pragma unroll
            for (int i = 0; i < 4; i++) ra[i] = As[k][ty * 4 + i];
#pragma unroll
            for (int j = 0; j < 4; j++) rb[j] = Bs[k][tx * 4 + j];
#pragma unroll
            for (int i = 0; i < 4; i++)
#pragma unroll
                for (int j = 0; j < 4; j++) acc[i][j] += ra[i] * rb[j];
        }
    }
#pragma unroll
    for (int i = 0; i < 4; i++) {
        int m = m0 + ty * 4 + i;
#pragma unroll
        for (int j = 0; j < 4; j++) {
            int n = n0 + tx * 4 + j;
            g_hw2[(size_t)m * UX + n] = acc[i][j] + b1[n] + b2[n];
        }
    }
}

// ================= score GEMM (mma.sync tf32 + cp.async) =====================
// M = B*T (BM=128 == one batch b), N = U, K = ENC. BM=128, BN=128, BK=32.
// A tiles [m][k] stride 36, B tiles [n][k] stride 36, 2-stage cp.async.
// smem bytes: As 2*18432 @0, Bs 2*18432 @36864, hw2s @73728, Vs @74240,
//             red @74752 (2560). total 77312.
#define SC_BS_OFF   36864
#define SC_HW2_OFF  73728
#define SC_VS_OFF   74240
#define SC_RED_OFF  74752
#define SC_SMEM_BYTES 77312
#define SC_STAGE    18432

__global__ void __launch_bounds__(256, 2)
k_score_tc(const float* __restrict__ V) {
    extern __shared__ char smraw[];
    uint32_t smu = smem_to_u32(smraw);
    float* smf   = (float*)smraw;
    float* hw2s  = (float*)(smraw + SC_HW2_OFF);
    float* Vs    = (float*)(smraw + SC_VS_OFF);
    float* red   = (float*)(smraw + SC_RED_OFF);

    int tid = threadIdx.x;
    int lane = tid & 31, wid = tid >> 5;
    int warp_m = wid & 1, warp_n = wid >> 1;
    int g = lane >> 2, tig = lane & 3;
    int b = blockIdx.y;
    int n0 = blockIdx.x * 128;

    if (tid < 128) {
        hw2s[tid] = g_hw2[(size_t)b * UX + n0 + tid];
        Vs[tid] = V[n0 + tid];
    }

    const float* encB = g_enct + (size_t)b * Tx * ENCX;
    const float* W1tB = g_W1t + (size_t)n0 * ENCX;

    // copy mapping: 1024 float4 per operand tile, 4 per thread
    int rw[4], c4[4];
#pragma unroll
    for (int i = 0; i < 4; i++) {
        int idx = i * 256 + tid;
        rw[i] = idx >> 3; c4[i] = idx & 7;
    }

#define SC_ISSUE(J) do { \
    int k0 = (J) * 32; int sb = (J) & 1; \
    uint32_t ab = smu + sb * SC_STAGE; \
    uint32_t bb = smu + SC_BS_OFF + sb * SC_STAGE; \
    _Pragma("unroll") \
    for (int i = 0; i < 4; i++) { \
        uint32_t off = (uint32_t)(rw[i] * ASTRIDE + c4[i] * 4) * 4; \
        cp_async16(ab + off, encB + (size_t)rw[i] * ENCX + k0 + c4[i] * 4); \
        cp_async16(bb + off, W1tB + (size_t)rw[i] * ENCX + k0 + c4[i] * 4); \
    } \
    CP_COMMIT(); } while (0)

    float acc[4][4][4] = {};

    SC_ISSUE(0);
    for (int j = 0; j < NKT; j++) {
        CP_WAIT0();
        __syncthreads();
        if (j + 1 < NKT) SC_ISSUE(j + 1);
        const float* Asb = smf + (j & 1) * (SC_STAGE / 4);
        const float* Bsb = smf + SC_BS_OFF / 4 + (j & 1) * (SC_STAGE / 4);
#pragma unroll
        for (int kk = 0; kk < 32; kk += 8) {
            unsigned afr[4][4], bfr[4][2];
#pragma unroll
            for (int i = 0; i < 4; i++) {
                int row = warp_m * 64 + i * 16 + g;
                afr[i][0] = __float_as_uint(Asb[row * ASTRIDE + kk + tig]);
                afr[i][1] = __float_as_uint(Asb[(row + 8) * ASTRIDE + kk + tig]);
                afr[i][2] = __float_as_uint(Asb[row * ASTRIDE + kk + tig + 4]);
                afr[i][3] = __float_as_uint(Asb[(row + 8) * ASTRIDE + kk + tig + 4]);
            }
#pragma unroll
            for (int jn = 0; jn < 4; jn++) {
                int col = warp_n * 32 + jn * 8 + g;
                bfr[jn][0] = __float_as_uint(Bsb[col * ASTRIDE + kk + tig]);
                bfr[jn][1] = __float_as_uint(Bsb[col * ASTRIDE + kk + tig + 4]);
            }
#pragma unroll
            for (int i = 0; i < 4; i++)
#pragma unroll
                for (int jn = 0; jn < 4; jn++) mma_tf32(acc[i][jn], afr[i], bfr[jn]);
        }
        __syncthreads();
    }

    // epilogue: per-row sum of tanh(acc + hw2)*V
#pragma unroll
    for (int i = 0; i < 4; i++) {
        float s0 = 0.f, s1 = 0.f;
#pragma unroll
        for (int jn = 0; jn < 4; jn++) {
            int nb = warp_n * 32 + jn * 8 + tig * 2;
#pragma unroll
            for (int c = 0; c < 2; c++) {
                int n = nb + c;
                s0 += tanhf(acc[i][jn][c] + hw2s[n]) * Vs[n];
                s1 += tanhf(acc[i][jn][2 + c] + hw2s[n]) * Vs[n];
            }
        }
        s0 += __shfl_xor_sync(0xffffffffu, s0, 1);
        s0 += __shfl_xor_sync(0xffffffffu, s0, 2);
        s1 += __shfl_xor_sync(0xffffffffu, s1, 1);
        s1 += __shfl_xor_sync(0xffffffffu, s1, 2);
        if (tig == 0) {
            int r0 = warp_m * 64 + i * 16 + g;
            red[r0 * 5 + warp_n] = s0;
            red[(r0 + 8) * 5 + warp_n] = s1;
        }
    }
    __syncthreads();
    if (tid < 128) {
        float s = red[tid * 5 + 0] + red[tid * 5 + 1] + red[tid * 5 + 2] + red[tid * 5 + 3];
        atomicAdd(&g_S[b * Tx + tid], s);
    }
}

// ---------------- softmax over T + emb gather ----------------
__global__ void k_softmax(const int* __restrict__ x, const float* __restrict__ E,
                          float* __restrict__ attn_out) {
    int b = blockIdx.x;
    int tid = threadIdx.x;
    __shared__ float sh[128];
    float s = g_S[b * Tx + tid];
    sh[tid] = s;
    __syncthreads();
    for (int off = 64; off; off >>= 1) {
        if (tid < off) sh[tid] = fmaxf(sh[tid], sh[tid + off]);
        __syncthreads();
    }
    float mx = sh[0];
    __syncthreads();
    float e = expf(s - mx);
    sh[tid] = e;
    __syncthreads();
    for (int off = 64; off; off >>= 1) {
        if (tid < off) sh[tid] = sh[tid] + sh[tid + off];
        __syncthreads();
    }
    float a = e / sh[0];
    g_attn[b * Tx + tid] = a;
    attn_out[b * Tx + tid] = a;
    int row = x[b];
    for (int e2 = tid; e2 < EMBX; e2 += 128)
        g_xt[(size_t)b * XDIM + ENCX + e2] = E[(size_t)row * EMBX + e2];
}

// ---------------- context ----------------
__global__ void k_ctx(const float* __restrict__ enc) {
    int b = blockIdx.x;
    int ec = blockIdx.y * 256 + threadIdx.x;
    __shared__ float attn_sh[128];
    if (threadIdx.x < 128) attn_sh[threadIdx.x] = g_attn[b * Tx + threadIdx.x];
    __syncthreads();
    const float* p = enc + (size_t)b * Tx * ENCX + ec;
    float c = 0.f;
#pragma unroll 8
    for (int t = 0; t < Tx; t++) c += attn_sh[t] * p[(size_t)t * ENCX];
    g_xt[(size_t)b * XDIM + ec] = c;
}

// ---------------- gates ----------------
__global__ void k_gate(const float* __restrict__ Wx, const float* __restrict__ bg) {
    __shared__ float As[16][64];
    __shared__ float Bs[16][64];
    int tid = threadIdx.x;
    int m0 = blockIdx.y * 64;
    int nv0 = blockIdx.x * 64;
    int na0 = (nv0 < UX) ? nv0 : nv0 + UX;
    int ar = tid >> 2, ac = (tid & 3) << 2;
    int br = tid >> 4, bc = (tid & 15) << 2;
    int ty = tid >> 4, tx = tid & 15;
    float acc[4][4] = {};
    for (int k0 = 0; k0 < XDIM; k0 += 16) {
        float4 av = *(const float4*)&g_xt[(size_t)(m0 + ar) * XDIM + k0 + ac];
        float4 bv = *(const float4*)&Wx[(size_t)(k0 + br) * WXN + na0 + bc];
        __syncthreads();
        As[ac + 0][ar] = av.x; As[ac + 1][ar] = av.y;
        As[ac + 2][ar] = av.z; As[ac + 3][ar] = av.w;
        *(float4*)&Bs[br][bc] = bv;
        __syncthreads();
#pragma unroll
        for (int k = 0; k < 16; k++) {
            float ra[4], rb[4];
#pragma unroll
            for (int i = 0; i < 4; i++) ra[i] = As[k][ty * 4 + i];
#pragma unroll
            for (int j = 0; j < 4; j++) rb[j] = Bs[k][tx * 4 + j];
#pragma unroll
            for (int i = 0; i < 4; i++)
#pragma unroll
                for (int j = 0; j < 4; j++) acc[i][j] += ra[i] * rb[j];
        }
    }
#pragma unroll
    for (int i = 0; i < 4; i++) {
        int m = m0 + ty * 4 + i;
#pragma unroll
        for (int j = 0; j < 4; j++) {
            int nv = nv0 + tx * 4 + j;
            int na = na0 + tx * 4 + j;
            g_gx[(size_t)m * GXN + nv] = acc[i][j] + bg[na];
        }
    }
}

// ---------------- state = (1 - sigmoid(gz)) * tanh(ghh); + tf32 copy ---------
__global__ void k_state(float* __restrict__ out_state) {
    int i = blockIdx.x * blockDim.x + threadIdx.x;
    if (i >= Bx * UX) return;
    int bb = i >> 10, u = i & 1023;
    float gz = g_gx[(size_t)bb * GXN + u];
    float gh = g_gx[(size_t)bb * GXN + UX + u];
    float z = 1.f / (1.f + expf(-gz));
    float st = (1.f - z) * tanhf(gh);
    out_state[i] = st;
    g_statet[i] = f2tf(st);
}

// ============ logits GEMM (mma.sync tf32 + cp.async) =========================
// M=256, N=32000, K=1024. BM=128, BN=128, BK=32. grid (250, 2).
// A tiles [m][k] stride 36 (2x18432B @0); B tiles [k][n] stride 136
// (2x17408B @36864). total 71680 B.
#define LG_BS_OFF   36864
#define LG_BSTAGE   17408
#define LG_SMEM_BYTES 71680

__global__ void __launch_bounds__(256, 2)
k_logits_tc(const float* __restrict__ Wfc, const float* __restrict__ bfc,
            float* __restrict__ C) {
    extern __shared__ char smraw[];
    uint32_t smu = smem_to_u32(smraw);
    float* smf = (float*)smraw;

    int tid = threadIdx.x;
    int lane = tid & 31, wid = tid >> 5;
    int warp_m = wid & 1, warp_n = wid >> 1;
    int g = lane >> 2, tig = lane & 3;
    int m0 = blockIdx.y * 128, n0 = blockIdx.x * 128;

    const float* Ab = g_statet + (size_t)m0 * UX;
    const float* Bb = Wfc + n0;

    int am[4], ak4[4], bk[4], bn4[4];
#pragma unroll
    for (int i = 0; i < 4; i++) {
        int idx = i * 256 + tid;
        am[i] = idx >> 3; ak4[i] = idx & 7;
        bk[i] = idx >> 5; bn4[i] = idx & 31;
    }

#define LG_ISSUE(J) do { \
    int k0 = (J) * 32; int sb = (J) & 1; \
    uint32_t ab = smu + sb * SC_STAGE; \
    uint32_t bb = smu + LG_BS_OFF + sb * LG_BSTAGE; \
    _Pragma("unroll") \
    for (int i = 0; i < 4; i++) { \
        cp_async16(ab + (uint32_t)(am[i] * ASTRIDE + ak4[i] * 4) * 4, \
                   Ab + (size_t)am[i] * UX + k0 + ak4[i] * 4); \
        cp_async16(bb + (uint32_t)(bk[i] * BSTRIDE + bn4[i] * 4) * 4, \
                   Bb + (size_t)(k0 + bk[i]) * VOCABX + bn4[i] * 4); \
    } \
    CP_COMMIT(); } while (0)

    float acc[4][4][4] = {};

    LG_ISSUE(0);
    for (int j = 0; j < NKT; j++) {
        CP_WAIT0();
        __syncthreads();
        if (j + 1 < NKT) LG_ISSUE(j + 1);
        const float* Asb = smf + (j & 1) * (SC_STAGE / 4);
        const float* Bsb = smf + LG_BS_OFF / 4 + (j & 1) * (LG_BSTAGE / 4);
#pragma unroll
        for (int kk = 0; kk < 32; kk += 8) {
            unsigned afr[4][4], bfr[4][2];
#pragma unroll
            for (int i = 0; i < 4; i++) {
                int row = warp_m * 64 + i * 16 + g;
                afr[i][0] = __float_as_uint(Asb[row * ASTRIDE + kk + tig]);
                afr[i][1] = __float_as_uint(Asb[(row + 8) * ASTRIDE + kk + tig]);
                afr[i][2] = __float_as_uint(Asb[row * ASTRIDE + kk + tig + 4]);
                afr[i][3] = __float_as_uint(Asb[(row + 8) * ASTRIDE + kk + tig + 4]);
            }
#pragma unroll
            for (int jn = 0; jn < 4; jn++) {
                int col = warp_n * 32 + jn * 8 + g;
                bfr[jn][0] = __float_as_uint(Bsb[(kk + tig) * BSTRIDE + col]);
                bfr[jn][1] = __float_as_uint(Bsb[(kk + tig + 4) * BSTRIDE + col]);
            }
#pragma unroll
            for (int i = 0; i < 4; i++)
#pragma unroll
                for (int jn = 0; jn < 4; jn++) mma_tf32(acc[i][jn], afr[i], bfr[jn]);
        }
        __syncthreads();
    }

#pragma unroll
    for (int i = 0; i < 4; i++) {
        int r = m0 + warp_m * 64 + i * 16 + g;
#pragma unroll
        for (int jn = 0; jn < 4; jn++) {
            int n = n0 + warp_n * 32 + jn * 8 + tig * 2;
            float bf0 = bfc[n], bf1 = bfc[n + 1];
            *(float2*)&C[(size_t)r * VOCABX + n] =
                make_float2(acc[i][jn][0] + bf0, acc[i][jn][1] + bf1);
            *(float2*)&C[(size_t)(r + 8) * VOCABX + n] =
                make_float2(acc[i][jn][2] + bf0, acc[i][jn][3] + bf1);
        }
    }
}

// ---------------- launcher ----------------
extern "C" void kernel_launch(void* const* d_in, const int* in_sizes, int n_in,
                              void* d_out, int out_size) {
    const int*   x      = (const int*)d_in[0];
    const float* hidden = (const float*)d_in[1];
    const float* enc    = (const float*)d_in[2];
    const float* E      = (const float*)d_in[3];
    const float* W1     = (const float*)d_in[4];
    const float* b1     = (const float*)d_in[5];
    const float* W2     = (const float*)d_in[6];
    const float* b2     = (const float*)d_in[7];
    const float* V      = (const float*)d_in[8];
    const float* Wx     = (const float*)d_in[10];
    const float* b_gru  = (const float*)d_in[12];
    const float* Wfc    = (const float*)d_in[13];
    const float* bfc    = (const float*)d_in[14];

    float* out        = (float*)d_out;
    float* out_logits = out;
    float* out_state  = out + (size_t)Bx * VOCABX;
    float* out_attn   = out + (size_t)Bx * VOCABX + Bx * UX;

    cudaFuncSetAttribute(k_score_tc, cudaFuncAttributeMaxDynamicSharedMemorySize,
                         SC_SMEM_BYTES);
    cudaFuncSetAttribute(k_logits_tc, cudaFuncAttributeMaxDynamicSharedMemorySize,
                         LG_SMEM_BYTES);

    k_zero_S<<<(Bx * Tx + 255) / 256, 256>>>();
    k_round_enc<<<(Bx * Tx * ENCX / 4 + 255) / 256, 256>>>(enc);
    k_transpose_W1<<<dim3(32, 32), dim3(32, 8)>>>(W1);
    k_hw2<<<dim3(UX / 64, Bx / 64), 256>>>(hidden, W2, b1, b2);
    k_score_tc<<<dim3(UX / 128, Bx), 256, SC_SMEM_BYTES>>>(V);
    k_softmax<<<Bx, 128>>>(x, E, out_attn);
    k_ctx<<<dim3(Bx, ENCX / 256), 256>>>(enc);
    k_gate<<<dim3(GXN / 64, Bx / 64), 256>>>(Wx, b_gru);
    k_state<<<(Bx * UX + 255) / 256, 256>>>(out_state);
    k_logits_tc<<<dim3(VOCABX / 128, Bx / 128), 256, LG_SMEM_BYTES>>>(
        Wfc, bfc, out_logits);
}

// round 6
// speedup vs baseline: 1.8219x; 1.1066x over previous
#include <cuda_runtime.h>
#include <cstdint>
#include <math.h>

#define Bx     256
#define Tx     128
#define ENCX   1024
#define UX     1024
#define EMBX   512
#define VOCABX 32000
#define XDIM   1536
#define WXN    3072
#define GXN    2048
#define NKT    32          // K tiles of 32 over K=1024
#define ASTRIDE 36         // 32 + 4 pad; 144B rows (16B-aligned, conflict-free frags)
#define BSTRIDE 136        // logits B tile: 128 + 8 pad

// ---------------- scratch ----------------
__device__ float g_hw2[Bx * UX];
__device__ float g_S[Bx * Tx];
__device__ float g_attn[Bx * Tx];
__device__ float g_xt[Bx * XDIM];
__device__ float g_gx[Bx * GXN];
__device__ float g_statet[Bx * UX];       // tf32-rounded state
__device__ float g_W1t[UX * ENCX];        // W1 transposed (N,K), tf32-rounded
__device__ float g_enct[Bx * Tx * ENCX];  // enc, tf32-rounded

__device__ __forceinline__ float f2tf(float f) {
    unsigned u;
    asm("cvt.rna.tf32.f32 %0, %1;" : "=r"(u) : "f"(f));
    return __uint_as_float(u);
}
__device__ __forceinline__ uint32_t smem_to_u32(const void* p) {
    uint32_t a;
    asm("{ .reg .u64 t; cvta.to.shared.u64 t, %1; cvt.u32.u64 %0, t; }"
        : "=r"(a) : "l"(p));
    return a;
}
__device__ __forceinline__ void cp_async16(uint32_t s, const void* g) {
    asm volatile("cp.async.ca.shared.global [%0], [%1], 16;" :: "r"(s), "l"(g));
}
#define CP_COMMIT() asm volatile("cp.async.commit_group;")
#define CP_WAIT0()  asm volatile("cp.async.wait_group 0;")

__device__ __forceinline__ void mma_tf32(float* c, const unsigned* a, const unsigned* b) {
    asm volatile(
        "mma.sync.aligned.m16n8k8.row.col.f32.tf32.tf32.f32 "
        "{%0,%1,%2,%3}, {%4,%5,%6,%7}, {%8,%9}, {%0,%1,%2,%3};"
        : "+f"(c[0]), "+f"(c[1]), "+f"(c[2]), "+f"(c[3])
        : "r"(a[0]), "r"(a[1]), "r"(a[2]), "r"(a[3]), "r"(b[0]), "r"(b[1]));
}

// ---------------- init: zero S, g_hw2 = b1 + b2 ----------------
__global__ void k_init(const float* __restrict__ b1, const float* __restrict__ b2) {
    int i = blockIdx.x * blockDim.x + threadIdx.x;
    if (i < Bx * UX) g_hw2[i] = b1[i & 1023] + b2[i & 1023];
    if (i < Bx * Tx) g_S[i] = 0.f;
}

// ---------------- round enc -> g_enct (tf32 RNA) ----------------
__global__ void k_round_enc(const float* __restrict__ enc) {
    size_t i = (size_t)(blockIdx.x * blockDim.x + threadIdx.x) * 4;
    size_t n = (size_t)Bx * Tx * ENCX;
    if (i >= n) return;
    float4 v = *(const float4*)(enc + i);
    v.x = f2tf(v.x); v.y = f2tf(v.y); v.z = f2tf(v.z); v.w = f2tf(v.w);
    *(float4*)(g_enct + i) = v;
}

// ---------------- transpose W1 -> g_W1t (N,K), tf32-rounded ----------------
__global__ void k_transpose_W1(const float* __restrict__ W1) {
    __shared__ float t[32][33];
    int bx = blockIdx.x * 32, by = blockIdx.y * 32;
    int x = threadIdx.x, y0 = threadIdx.y;
#pragma unroll
    for (int i = 0; i < 32; i += 8)
        t[y0 + i][x] = W1[(size_t)(by + y0 + i) * UX + bx + x];
    __syncthreads();
#pragma unroll
    for (int i = 0; i < 32; i += 8)
        g_W1t[(size_t)(bx + y0 + i) * ENCX + by + x] = f2tf(t[x][y0 + i]);
}

// ---------------- hw2 += hidden @ W2 (split-K x4) ----------------
// 64x64 tile, K slice of 256 per bz. grid (16, 4, 4). atomicAdd epilogue.
__global__ void k_hw2(const float* __restrict__ hidden, const float* __restrict__ W2) {
    __shared__ float As[16][64];
    __shared__ float Bs[16][64];
    int tid = threadIdx.x;
    int m0 = blockIdx.y * 64, n0 = blockIdx.x * 64;
    int kbase = blockIdx.z * 256;
    int ar = tid >> 2, ac = (tid & 3) << 2;
    int br = tid >> 4, bc = (tid & 15) << 2;
    int ty = tid >> 4, tx = tid & 15;
    float acc[4][4] = {};
    for (int k0 = kbase; k0 < kbase + 256; k0 += 16) {
        float4 av = *(const float4*)&hidden[(size_t)(m0 + ar) * UX + k0 + ac];
        float4 bv = *(const float4*)&W2[(size_t)(k0 + br) * UX + n0 + bc];
        __syncthreads();
        As[ac + 0][ar] = av.x; As[ac + 1][ar] = av.y;
        As[ac + 2][ar] = av.z; As[ac + 3][ar] = av.w;
        *(float4*)&Bs[br][bc] = bv;
        __syncthreads();
#pragma unroll
        for (int k = 0; k < 16; k++) {
            float ra[4], rb[4];
#pragma unroll
            for (int i = 0; i < 4; i++) ra[i] = As[k][ty * 4 + i];
#pragma unroll
            for (int j = 0; j < 4; j++) rb[j] = Bs[k][tx * 4 + j];
#pragma unroll
            for (int i = 0; i < 4; i++)
#pragma unroll
                for (int j = 0; j < 4; j++) acc[i][j] += ra[i] * rb[j];
        }
    }
#pragma unroll
    for (int i = 0; i < 4; i++) {
        int m = m0 + ty * 4 + i;
#pragma unroll
        for (int j = 0; j < 4; j++)
            atomicAdd(&g_hw2[(size_t)m * UX + n0 + tx * 4 + j], acc[i][j]);
    }
}

// ================= score GEMM (mma.sync tf32 + cp.async) =====================
// M = B*T (BM=128 == one batch b), N = U, K = ENC. BM=128, BN=128, BK=32.
// 128 threads, 4 warps in 2(m) x 2(n); warptile 64x64 -> LDS:MMA = 1:1.
// A tiles [m][k] stride 36, B tiles [n][k] stride 36, 2-stage cp.async.
// smem: As 2*18432 @0, Bs 2*18432 @36864, hw2s @73728, Vs @74240,
//       red[128*3] @74752. total 76288.
#define SC_BS_OFF   36864
#define SC_HW2_OFF  73728
#define SC_VS_OFF   74240
#define SC_RED_OFF  74752
#define SC_SMEM_BYTES 76288
#define SC_STAGE    18432

__global__ void __launch_bounds__(128, 2)
k_score_tc(const float* __restrict__ V) {
    extern __shared__ char smraw[];
    uint32_t smu = smem_to_u32(smraw);
    float* smf   = (float*)smraw;
    float* hw2s  = (float*)(smraw + SC_HW2_OFF);
    float* Vs    = (float*)(smraw + SC_VS_OFF);
    float* red   = (float*)(smraw + SC_RED_OFF);

    int tid = threadIdx.x;
    int lane = tid & 31, wid = tid >> 5;
    int warp_m = wid & 1, warp_n = wid >> 1;   // 2 x 2 warps
    int g = lane >> 2, tig = lane & 3;
    int b = blockIdx.y;
    int n0 = blockIdx.x * 128;

    hw2s[tid] = g_hw2[(size_t)b * UX + n0 + tid];
    Vs[tid] = V[n0 + tid];

    const float* encB = g_enct + (size_t)b * Tx * ENCX;
    const float* W1tB = g_W1t + (size_t)n0 * ENCX;

    // copy mapping: 1024 float4 per operand tile, 8 per thread each
    int rw[8], c4[8];
#pragma unroll
    for (int i = 0; i < 8; i++) {
        int idx = i * 128 + tid;
        rw[i] = idx >> 3; c4[i] = idx & 7;
    }

#define SC_ISSUE(J) do { \
    int k0 = (J) * 32; int sb = (J) & 1; \
    uint32_t ab = smu + sb * SC_STAGE; \
    uint32_t bb = smu + SC_BS_OFF + sb * SC_STAGE; \
    _Pragma("unroll") \
    for (int i = 0; i < 8; i++) { \
        uint32_t off = (uint32_t)(rw[i] * ASTRIDE + c4[i] * 4) * 4; \
        cp_async16(ab + off, encB + (size_t)rw[i] * ENCX + k0 + c4[i] * 4); \
        cp_async16(bb + off, W1tB + (size_t)rw[i] * ENCX + k0 + c4[i] * 4); \
    } \
    CP_COMMIT(); } while (0)

    float acc[4][8][4] = {};

    SC_ISSUE(0);
    for (int j = 0; j < NKT; j++) {
        CP_WAIT0();
        __syncthreads();
        if (j + 1 < NKT) SC_ISSUE(j + 1);
        const float* Asb = smf + (j & 1) * (SC_STAGE / 4);
        const float* Bsb = smf + SC_BS_OFF / 4 + (j & 1) * (SC_STAGE / 4);
#pragma unroll
        for (int kk = 0; kk < 32; kk += 8) {
            unsigned afr[4][4], bfr[8][2];
#pragma unroll
            for (int i = 0; i < 4; i++) {
                int row = warp_m * 64 + i * 16 + g;
                afr[i][0] = __float_as_uint(Asb[row * ASTRIDE + kk + tig]);
                afr[i][1] = __float_as_uint(Asb[(row + 8) * ASTRIDE + kk + tig]);
                afr[i][2] = __float_as_uint(Asb[row * ASTRIDE + kk + tig + 4]);
                afr[i][3] = __float_as_uint(Asb[(row + 8) * ASTRIDE + kk + tig + 4]);
            }
#pragma unroll
            for (int jn = 0; jn < 8; jn++) {
                int col = warp_n * 64 + jn * 8 + g;
                bfr[jn][0] = __float_as_uint(Bsb[col * ASTRIDE + kk + tig]);
                bfr[jn][1] = __float_as_uint(Bsb[col * ASTRIDE + kk + tig + 4]);
            }
#pragma unroll
            for (int i = 0; i < 4; i++)
#pragma unroll
                for (int jn = 0; jn < 8; jn++) mma_tf32(acc[i][jn], afr[i], bfr[jn]);
        }
        __syncthreads();
    }

    // epilogue: per-row sum of tanh(acc + hw2)*V
#pragma unroll
    for (int i = 0; i < 4; i++) {
        float s0 = 0.f, s1 = 0.f;
#pragma unroll
        for (int jn = 0; jn < 8; jn++) {
            int nb = warp_n * 64 + jn * 8 + tig * 2;
#pragma unroll
            for (int c = 0; c < 2; c++) {
                int n = nb + c;
                s0 += tanhf(acc[i][jn][c] + hw2s[n]) * Vs[n];
                s1 += tanhf(acc[i][jn][2 + c] + hw2s[n]) * Vs[n];
            }
        }
        s0 += __shfl_xor_sync(0xffffffffu, s0, 1);
        s0 += __shfl_xor_sync(0xffffffffu, s0, 2);
        s1 += __shfl_xor_sync(0xffffffffu, s1, 1);
        s1 += __shfl_xor_sync(0xffffffffu, s1, 2);
        if (tig == 0) {
            int r0 = warp_m * 64 + i * 16 + g;
            red[r0 * 3 + warp_n] = s0;
            red[(r0 + 8) * 3 + warp_n] = s1;
        }
    }
    __syncthreads();
    atomicAdd(&g_S[b * Tx + tid], red[tid * 3 + 0] + red[tid * 3 + 1]);
}

// ---------------- softmax over T + emb gather ----------------
__global__ void k_softmax(const int* __restrict__ x, const float* __restrict__ E,
                          float* __restrict__ attn_out) {
    int b = blockIdx.x;
    int tid = threadIdx.x;
    __shared__ float sh[128];
    float s = g_S[b * Tx + tid];
    sh[tid] = s;
    __syncthreads();
    for (int off = 64; off; off >>= 1) {
        if (tid < off) sh[tid] = fmaxf(sh[tid], sh[tid + off]);
        __syncthreads();
    }
    float mx = sh[0];
    __syncthreads();
    float e = expf(s - mx);
    sh[tid] = e;
    __syncthreads();
    for (int off = 64; off; off >>= 1) {
        if (tid < off) sh[tid] = sh[tid] + sh[tid + off];
        __syncthreads();
    }
    float a = e / sh[0];
    g_attn[b * Tx + tid] = a;
    attn_out[b * Tx + tid] = a;
    int row = x[b];
    for (int e2 = tid; e2 < EMBX; e2 += 128)
        g_xt[(size_t)b * XDIM + ENCX + e2] = E[(size_t)row * EMBX + e2];
}

// ---------------- context ----------------
__global__ void k_ctx(const float* __restrict__ enc) {
    int b = blockIdx.x;
    int ec = blockIdx.y * 256 + threadIdx.x;
    __shared__ float attn_sh[128];
    if (threadIdx.x < 128) attn_sh[threadIdx.x] = g_attn[b * Tx + threadIdx.x];
    __syncthreads();
    const float* p = enc + (size_t)b * Tx * ENCX + ec;
    float c = 0.f;
#pragma unroll 8
    for (int t = 0; t < Tx; t++) c += attn_sh[t] * p[(size_t)t * ENCX];
    g_xt[(size_t)b * XDIM + ec] = c;
}

// ---------------- gates ----------------
__global__ void k_gate(const float* __restrict__ Wx, const float* __restrict__ bg) {
    __shared__ float As[16][64];
    __shared__ float Bs[16][64];
    int tid = threadIdx.x;
    int m0 = blockIdx.y * 64;
    int nv0 = blockIdx.x * 64;
    int na0 = (nv0 < UX) ? nv0 : nv0 + UX;
    int ar = tid >> 2, ac = (tid & 3) << 2;
    int br = tid >> 4, bc = (tid & 15) << 2;
    int ty = tid >> 4, tx = tid & 15;
    float acc[4][4] = {};
    for (int k0 = 0; k0 < XDIM; k0 += 16) {
        float4 av = *(const float4*)&g_xt[(size_t)(m0 + ar) * XDIM + k0 + ac];
        float4 bv = *(const float4*)&Wx[(size_t)(k0 + br) * WXN + na0 + bc];
        __syncthreads();
        As[ac + 0][ar] = av.x; As[ac + 1][ar] = av.y;
        As[ac + 2][ar] = av.z; As[ac + 3][ar] = av.w;
        *(float4*)&Bs[br][bc] = bv;
        __syncthreads();
#pragma unroll
        for (int k = 0; k < 16; k++) {
            float ra[4], rb[4];
#pragma unroll
            for (int i = 0; i < 4; i++) ra[i] = As[k][ty * 4 + i];
#pragma unroll
            for (int j = 0; j < 4; j++) rb[j] = Bs[k][tx * 4 + j];
#pragma unroll
            for (int i = 0; i < 4; i++)
#pragma unroll
                for (int j = 0; j < 4; j++) acc[i][j] += ra[i] * rb[j];
        }
    }
#pragma unroll
    for (int i = 0; i < 4; i++) {
        int m = m0 + ty * 4 + i;
#pragma unroll
        for (int j = 0; j < 4; j++) {
            int nv = nv0 + tx * 4 + j;
            int na = na0 + tx * 4 + j;
            g_gx[(size_t)m * GXN + nv] = acc[i][j] + bg[na];
        }
    }
}

// ---------------- state = (1 - sigmoid(gz)) * tanh(ghh); + tf32 copy ---------
__global__ void k_state(float* __restrict__ out_state) {
    int i = blockIdx.x * blockDim.x + threadIdx.x;
    if (i >= Bx * UX) return;
    int bb = i >> 10, u = i & 1023;
    float gz = g_gx[(size_t)bb * GXN + u];
    float gh = g_gx[(size_t)bb * GXN + UX + u];
    float z = 1.f / (1.f + expf(-gz));
    float st = (1.f - z) * tanhf(gh);
    out_state[i] = st;
    g_statet[i] = f2tf(st);
}

// ============ logits GEMM (mma.sync tf32 + cp.async) =========================
// M=256, N=32000, K=1024. BM=128, BN=128, BK=32. grid (250, 2). 256 threads.
#define LG_BS_OFF   36864
#define LG_BSTAGE   17408
#define LG_SMEM_BYTES 71680

__global__ void __launch_bounds__(256, 2)
k_logits_tc(const float* __restrict__ Wfc, const float* __restrict__ bfc,
            float* __restrict__ C) {
    extern __shared__ char smraw[];
    uint32_t smu = smem_to_u32(smraw);
    float* smf = (float*)smraw;

    int tid = threadIdx.x;
    int lane = tid & 31, wid = tid >> 5;
    int warp_m = wid & 1, warp_n = wid >> 1;
    int g = lane >> 2, tig = lane & 3;
    int m0 = blockIdx.y * 128, n0 = blockIdx.x * 128;

    const float* Ab = g_statet + (size_t)m0 * UX;
    const float* Bb = Wfc + n0;

    int am[4], ak4[4], bk[4], bn4[4];
#pragma unroll
    for (int i = 0; i < 4; i++) {
        int idx = i * 256 + tid;
        am[i] = idx >> 3; ak4[i] = idx & 7;
        bk[i] = idx >> 5; bn4[i] = idx & 31;
    }

#define LG_ISSUE(J) do { \
    int k0 = (J) * 32; int sb = (J) & 1; \
    uint32_t ab = smu + sb * SC_STAGE; \
    uint32_t bb = smu + LG_BS_OFF + sb * LG_BSTAGE; \
    _Pragma("unroll") \
    for (int i = 0; i < 4; i++) { \
        cp_async16(ab + (uint32_t)(am[i] * ASTRIDE + ak4[i] * 4) * 4, \
                   Ab + (size_t)am[i] * UX + k0 + ak4[i] * 4); \
        cp_async16(bb + (uint32_t)(bk[i] * BSTRIDE + bn4[i] * 4) * 4, \
                   Bb + (size_t)(k0 + bk[i]) * VOCABX + bn4[i] * 4); \
    } \
    CP_COMMIT(); } while (0)

    float acc[4][4][4] = {};

    LG_ISSUE(0);
    for (int j = 0; j < NKT; j++) {
        CP_WAIT0();
        __syncthreads();
        if (j + 1 < NKT) LG_ISSUE(j + 1);
        const float* Asb = smf + (j & 1) * (SC_STAGE / 4);
        const float* Bsb = smf + LG_BS_OFF / 4 + (j & 1) * (LG_BSTAGE / 4);
#pragma unroll
        for (int kk = 0; kk < 32; kk += 8) {
            unsigned afr[4][4], bfr[4][2];
#pragma unroll
            for (int i = 0; i < 4; i++) {
                int row = warp_m * 64 + i * 16 + g;
                afr[i][0] = __float_as_uint(Asb[row * ASTRIDE + kk + tig]);
                afr[i][1] = __float_as_uint(Asb[(row + 8) * ASTRIDE + kk + tig]);
                afr[i][2] = __float_as_uint(Asb[row * ASTRIDE + kk + tig + 4]);
                afr[i][3] = __float_as_uint(Asb[(row + 8) * ASTRIDE + kk + tig + 4]);
            }
#pragma unroll
            for (int jn = 0; jn < 4; jn++) {
                int col = warp_n * 32 + jn * 8 + g;
                bfr[jn][0] = __float_as_uint(Bsb[(kk + tig) * BSTRIDE + col]);
                bfr[jn][1] = __float_as_uint(Bsb[(kk + tig + 4) * BSTRIDE + col]);
            }
#pragma unroll
            for (int i = 0; i < 4; i++)
#pragma unroll
                for (int jn = 0; jn < 4; jn++) mma_tf32(acc[i][jn], afr[i], bfr[jn]);
        }
        __syncthreads();
    }

#pragma unroll
    for (int i = 0; i < 4; i++) {
        int r = m0 + warp_m * 64 + i * 16 + g;
#pragma unroll
        for (int jn = 0; jn < 4; jn++) {
            int n = n0 + warp_n * 32 + jn * 8 + tig * 2;
            float bf0 = bfc[n], bf1 = bfc[n + 1];
            *(float2*)&C[(size_t)r * VOCABX + n] =
                make_float2(acc[i][jn][0] + bf0, acc[i][jn][1] + bf1);
            *(float2*)&C[(size_t)(r + 8) * VOCABX + n] =
                make_float2(acc[i][jn][2] + bf0, acc[i][jn][3] + bf1);
        }
    }
}

// ---------------- launcher ----------------
extern "C" void kernel_launch(void* const* d_in, const int* in_sizes, int n_in,
                              void* d_out, int out_size) {
    const int*   x      = (const int*)d_in[0];
    const float* hidden = (const float*)d_in[1];
    const float* enc    = (const float*)d_in[2];
    const float* E      = (const float*)d_in[3];
    const float* W1     = (const float*)d_in[4];
    const float* b1     = (const float*)d_in[5];
    const float* W2     = (const float*)d_in[6];
    const float* b2     = (const float*)d_in[7];
    const float* V      = (const float*)d_in[8];
    const float* Wx     = (const float*)d_in[10];
    const float* b_gru  = (const float*)d_in[12];
    const float* Wfc    = (const float*)d_in[13];
    const float* bfc    = (const float*)d_in[14];

    float* out        = (float*)d_out;
    float* out_logits = out;
    float* out_state  = out + (size_t)Bx * VOCABX;
    float* out_attn   = out + (size_t)Bx * VOCABX + Bx * UX;

    cudaFuncSetAttribute(k_score_tc, cudaFuncAttributeMaxDynamicSharedMemorySize,
                         SC_SMEM_BYTES);
    cudaFuncSetAttribute(k_logits_tc, cudaFuncAttributeMaxDynamicSharedMemorySize,
                         LG_SMEM_BYTES);

    k_init<<<(Bx * UX + 255) / 256, 256>>>(b1, b2);
    k_round_enc<<<(Bx * Tx * ENCX / 4 + 255) / 256, 256>>>(enc);
    k_transpose_W1<<<dim3(32, 32), dim3(32, 8)>>>(W1);
    k_hw2<<<dim3(16, 4, 4), 256>>>(hidden, W2);
    k_score_tc<<<dim3(UX / 128, Bx), 128, SC_SMEM_BYTES>>>(V);
    k_softmax<<<Bx, 128>>>(x, E, out_attn);
    k_ctx<<<dim3(Bx, ENCX / 256), 256>>>(enc);
    k_gate<<<dim3(GXN / 64, Bx / 64), 256>>>(Wx, b_gru);
    k_state<<<(Bx * UX + 255) / 256, 256>>>(out_state);
    k_logits_tc<<<dim3(VOCABX / 128, Bx / 128), 256, LG_SMEM_BYTES>>>(
        Wfc, bfc, out_logits);
}

// round 7
// speedup vs baseline: 1.8644x; 1.0233x over previous
#include <cuda_runtime.h>
#include <cstdint>
#include <math.h>

#define Bx     256
#define Tx     128
#define ENCX   1024
#define UX     1024
#define EMBX   512
#define VOCABX 32000
#define XDIM   1536
#define WXN    3072
#define GXN    2048
#define NKT    32          // K tiles of 32 over K=1024
#define ASTRIDE 36         // 32 + 4 pad; conflict-free frags
#define BSTRIDE 136        // logits B tile: 128 + 8 pad

// ---------------- scratch ----------------
__device__ float g_hw2[Bx * UX];
__device__ float g_S[Bx * Tx];
__device__ float g_attn[Bx * Tx];
__device__ float g_xt[Bx * XDIM];
__device__ float g_gx[Bx * GXN];
__device__ float g_statet[Bx * UX];       // tf32-rounded state
__device__ float g_W1t[UX * ENCX];        // W1 transposed (N,K), tf32-rounded
__device__ float g_enct[Bx * Tx * ENCX];  // enc, tf32-rounded

__device__ __forceinline__ float f2tf(float f) {
    unsigned u;
    asm("cvt.rna.tf32.f32 %0, %1;" : "=r"(u) : "f"(f));
    return __uint_as_float(u);
}
__device__ __forceinline__ uint32_t smem_to_u32(const void* p) {
    uint32_t a;
    asm("{ .reg .u64 t; cvta.to.shared.u64 t, %1; cvt.u32.u64 %0, t; }"
        : "=r"(a) : "l"(p));
    return a;
}
__device__ __forceinline__ void cp_async16(uint32_t s, const void* g) {
    asm volatile("cp.async.ca.shared.global [%0], [%1], 16;" :: "r"(s), "l"(g));
}
#define CP_COMMIT() asm volatile("cp.async.commit_group;")
#define CP_WAIT0()  asm volatile("cp.async.wait_group 0;")

__device__ __forceinline__ void mma_tf32(float* c, const unsigned* a, const unsigned* b) {
    asm volatile(
        "mma.sync.aligned.m16n8k8.row.col.f32.tf32.tf32.f32 "
        "{%0,%1,%2,%3}, {%4,%5,%6,%7}, {%8,%9}, {%0,%1,%2,%3};"
        : "+f"(c[0]), "+f"(c[1]), "+f"(c[2]), "+f"(c[3])
        : "r"(a[0]), "r"(a[1]), "r"(a[2]), "r"(a[3]), "r"(b[0]), "r"(b[1]));
}

// ---------------- init: zero S, g_hw2 = b1 + b2 ----------------
__global__ void k_init(const float* __restrict__ b1, const float* __restrict__ b2) {
    int i = blockIdx.x * blockDim.x + threadIdx.x;
    if (i < Bx * UX) g_hw2[i] = b1[i & 1023] + b2[i & 1023];
    if (i < Bx * Tx) g_S[i] = 0.f;
}

// ---------------- round enc -> g_enct (tf32 RNA) ----------------
__global__ void k_round_enc(const float* __restrict__ enc) {
    size_t i = (size_t)(blockIdx.x * blockDim.x + threadIdx.x) * 4;
    size_t n = (size_t)Bx * Tx * ENCX;
    if (i >= n) return;
    float4 v = *(const float4*)(enc + i);
    v.x = f2tf(v.x); v.y = f2tf(v.y); v.z = f2tf(v.z); v.w = f2tf(v.w);
    *(float4*)(g_enct + i) = v;
}

// ---------------- transpose W1 -> g_W1t (N,K), tf32-rounded ----------------
__global__ void k_transpose_W1(const float* __restrict__ W1) {
    __shared__ float t[32][33];
    int bx = blockIdx.x * 32, by = blockIdx.y * 32;
    int x = threadIdx.x, y0 = threadIdx.y;
#pragma unroll
    for (int i = 0; i < 32; i += 8)
        t[y0 + i][x] = W1[(size_t)(by + y0 + i) * UX + bx + x];
    __syncthreads();
#pragma unroll
    for (int i = 0; i < 32; i += 8)
        g_W1t[(size_t)(bx + y0 + i) * ENCX + by + x] = f2tf(t[x][y0 + i]);
}

// ---------------- hw2 += hidden @ W2 (split-K x8) ----------------
__global__ void k_hw2(const float* __restrict__ hidden, const float* __restrict__ W2) {
    __shared__ float As[16][64];
    __shared__ float Bs[16][64];
    int tid = threadIdx.x;
    int m0 = blockIdx.y * 64, n0 = blockIdx.x * 64;
    int kbase = blockIdx.z * 128;
    int ar = tid >> 2, ac = (tid & 3) << 2;
    int br = tid >> 4, bc = (tid & 15) << 2;
    int ty = tid >> 4, tx = tid & 15;
    float acc[4][4] = {};
    for (int k0 = kbase; k0 < kbase + 128; k0 += 16) {
        float4 av = *(const float4*)&hidden[(size_t)(m0 + ar) * UX + k0 + ac];
        float4 bv = *(const float4*)&W2[(size_t)(k0 + br) * UX + n0 + bc];
        __syncthreads();
        As[ac + 0][ar] = av.x; As[ac + 1][ar] = av.y;
        As[ac + 2][ar] = av.z; As[ac + 3][ar] = av.w;
        *(float4*)&Bs[br][bc] = bv;
        __syncthreads();
#pragma unroll
        for (int k = 0; k < 16; k++) {
            float ra[4], rb[4];
#pragma unroll
            for (int i = 0; i < 4; i++) ra[i] = As[k][ty * 4 + i];
#pragma unroll
            for (int j = 0; j < 4; j++) rb[j] = Bs[k][tx * 4 + j];
#pragma unroll
            for (int i = 0; i < 4; i++)
#pragma unroll
                for (int j = 0; j < 4; j++) acc[i][j] += ra[i] * rb[j];
        }
    }
#pragma unroll
    for (int i = 0; i < 4; i++) {
        int m = m0 + ty * 4 + i;
#pragma unroll
        for (int j = 0; j < 4; j++)
            atomicAdd(&g_hw2[(size_t)m * UX + n0 + tx * 4 + j], acc[i][j]);
    }
}

// ================= score GEMM (mma.sync tf32 + cp.async) =====================
// Block tile 128(m) x 256(n), BK=32. 256 threads, 8 warps 2(m) x 4(n),
// warptile 64x64. 1 CTA/SM. A [m][k] & B [n][k] tiles stride 36. 2 stages.
// smem: A 2*18432 @0, B 2*36864 @36864, hw2s[256] @110592, Vs[256] @111616,
//       red[128*5] @112640. total 115200.
#define SC_BS_OFF   36864
#define SC_STAGE_A  18432
#define SC_STAGE_B  36864
#define SC_HW2_OFF  110592
#define SC_VS_OFF   111616
#define SC_RED_OFF  112640
#define SC_SMEM_BYTES 115200

__global__ void __launch_bounds__(256, 1)
k_score_tc(const float* __restrict__ V) {
    extern __shared__ char smraw[];
    uint32_t smu = smem_to_u32(smraw);
    float* smf   = (float*)smraw;
    float* hw2s  = (float*)(smraw + SC_HW2_OFF);
    float* Vs    = (float*)(smraw + SC_VS_OFF);
    float* red   = (float*)(smraw + SC_RED_OFF);

    int tid = threadIdx.x;
    int lane = tid & 31, wid = tid >> 5;
    int warp_m = wid & 1, warp_n = wid >> 1;   // 2 x 4 warps
    int g = lane >> 2, tig = lane & 3;
    int b = blockIdx.y;
    int n0 = blockIdx.x * 256;

    hw2s[tid] = g_hw2[(size_t)b * UX + n0 + tid];
    Vs[tid] = V[n0 + tid];

    const float* encB = g_enct + (size_t)b * Tx * ENCX;
    const float* W1tB = g_W1t + (size_t)n0 * ENCX;

    // A: 1024 float4 (4/thread); B: 2048 float4 (8/thread)
    int arw[4], ac4[4], brw[8], bc4[8];
#pragma unroll
    for (int i = 0; i < 4; i++) {
        int idx = i * 256 + tid;
        arw[i] = idx >> 3; ac4[i] = idx & 7;
    }
#pragma unroll
    for (int i = 0; i < 8; i++) {
        int idx = i * 256 + tid;
        brw[i] = idx >> 3; bc4[i] = idx & 7;
    }

#define SC_ISSUE(J) do { \
    int k0 = (J) * 32; int sb = (J) & 1; \
    uint32_t ab = smu + sb * SC_STAGE_A; \
    uint32_t bb = smu + SC_BS_OFF + sb * SC_STAGE_B; \
    _Pragma("unroll") \
    for (int i = 0; i < 4; i++) \
        cp_async16(ab + (uint32_t)(arw[i] * ASTRIDE + ac4[i] * 4) * 4, \
                   encB + (size_t)arw[i] * ENCX + k0 + ac4[i] * 4); \
    _Pragma("unroll") \
    for (int i = 0; i < 8; i++) \
        cp_async16(bb + (uint32_t)(brw[i] * ASTRIDE + bc4[i] * 4) * 4, \
                   W1tB + (size_t)brw[i] * ENCX + k0 + bc4[i] * 4); \
    CP_COMMIT(); } while (0)

    float acc[4][8][4] = {};

    SC_ISSUE(0);
    for (int j = 0; j < NKT; j++) {
        CP_WAIT0();
        __syncthreads();
        if (j + 1 < NKT) SC_ISSUE(j + 1);
        const float* Asb = smf + (j & 1) * (SC_STAGE_A / 4);
        const float* Bsb = smf + SC_BS_OFF / 4 + (j & 1) * (SC_STAGE_B / 4);
#pragma unroll
        for (int kk = 0; kk < 32; kk += 8) {
            unsigned afr[4][4], bfr[8][2];
#pragma unroll
            for (int i = 0; i < 4; i++) {
                int row = warp_m * 64 + i * 16 + g;
                afr[i][0] = __float_as_uint(Asb[row * ASTRIDE + kk + tig]);
                afr[i][1] = __float_as_uint(Asb[(row + 8) * ASTRIDE + kk + tig]);
                afr[i][2] = __float_as_uint(Asb[row * ASTRIDE + kk + tig + 4]);
                afr[i][3] = __float_as_uint(Asb[(row + 8) * ASTRIDE + kk + tig + 4]);
            }
#pragma unroll
            for (int jn = 0; jn < 8; jn++) {
                int col = warp_n * 64 + jn * 8 + g;
                bfr[jn][0] = __float_as_uint(Bsb[col * ASTRIDE + kk + tig]);
                bfr[jn][1] = __float_as_uint(Bsb[col * ASTRIDE + kk + tig + 4]);
            }
#pragma unroll
            for (int i = 0; i < 4; i++)
#pragma unroll
                for (int jn = 0; jn < 8; jn++) mma_tf32(acc[i][jn], afr[i], bfr[jn]);
        }
    }

    __syncthreads();
    // epilogue: per-row sum of tanh(acc + hw2)*V
#pragma unroll
    for (int i = 0; i < 4; i++) {
        float s0 = 0.f, s1 = 0.f;
#pragma unroll
        for (int jn = 0; jn < 8; jn++) {
            int nb = warp_n * 64 + jn * 8 + tig * 2;
#pragma unroll
            for (int c = 0; c < 2; c++) {
                int n = nb + c;
                s0 += tanhf(acc[i][jn][c] + hw2s[n]) * Vs[n];
                s1 += tanhf(acc[i][jn][2 + c] + hw2s[n]) * Vs[n];
            }
        }
        s0 += __shfl_xor_sync(0xffffffffu, s0, 1);
        s0 += __shfl_xor_sync(0xffffffffu, s0, 2);
        s1 += __shfl_xor_sync(0xffffffffu, s1, 1);
        s1 += __shfl_xor_sync(0xffffffffu, s1, 2);
        if (tig == 0) {
            int r0 = warp_m * 64 + i * 16 + g;
            red[r0 * 5 + warp_n] = s0;
            red[(r0 + 8) * 5 + warp_n] = s1;
        }
    }
    __syncthreads();
    if (tid < 128) {
        float s = red[tid * 5 + 0] + red[tid * 5 + 1] + red[tid * 5 + 2] + red[tid * 5 + 3];
        atomicAdd(&g_S[b * Tx + tid], s);
    }
}

// ---------------- softmax over T + emb gather ----------------
__global__ void k_softmax(const int* __restrict__ x, const float* __restrict__ E,
                          float* __restrict__ attn_out) {
    int b = blockIdx.x;
    int tid = threadIdx.x;
    __shared__ float sh[128];
    float s = g_S[b * Tx + tid];
    sh[tid] = s;
    __syncthreads();
    for (int off = 64; off; off >>= 1) {
        if (tid < off) sh[tid] = fmaxf(sh[tid], sh[tid + off]);
        __syncthreads();
    }
    float mx = sh[0];
    __syncthreads();
    float e = expf(s - mx);
    sh[tid] = e;
    __syncthreads();
    for (int off = 64; off; off >>= 1) {
        if (tid < off) sh[tid] = sh[tid] + sh[tid + off];
        __syncthreads();
    }
    float a = e / sh[0];
    g_attn[b * Tx + tid] = a;
    attn_out[b * Tx + tid] = a;
    int row = x[b];
    for (int e2 = tid; e2 < EMBX; e2 += 128)
        g_xt[(size_t)b * XDIM + ENCX + e2] = E[(size_t)row * EMBX + e2];
}

// ---------------- context ----------------
__global__ void k_ctx(const float* __restrict__ enc) {
    int b = blockIdx.x;
    int ec = blockIdx.y * 256 + threadIdx.x;
    __shared__ float attn_sh[128];
    if (threadIdx.x < 128) attn_sh[threadIdx.x] = g_attn[b * Tx + threadIdx.x];
    __syncthreads();
    const float* p = enc + (size_t)b * Tx * ENCX + ec;
    float c = 0.f;
#pragma unroll 8
    for (int t = 0; t < Tx; t++) c += attn_sh[t] * p[(size_t)t * ENCX];
    g_xt[(size_t)b * XDIM + ec] = c;
}

// ---------------- gates ----------------
__global__ void k_gate(const float* __restrict__ Wx, const float* __restrict__ bg) {
    __shared__ float As[16][64];
    __shared__ float Bs[16][64];
    int tid = threadIdx.x;
    int m0 = blockIdx.y * 64;
    int nv0 = blockIdx.x * 64;
    int na0 = (nv0 < UX) ? nv0 : nv0 + UX;
    int ar = tid >> 2, ac = (tid & 3) << 2;
    int br = tid >> 4, bc = (tid & 15) << 2;
    int ty = tid >> 4, tx = tid & 15;
    float acc[4][4] = {};
    for (int k0 = 0; k0 < XDIM; k0 += 16) {
        float4 av = *(const float4*)&g_xt[(size_t)(m0 + ar) * XDIM + k0 + ac];
        float4 bv = *(const float4*)&Wx[(size_t)(k0 + br) * WXN + na0 + bc];
        __syncthreads();
        As[ac + 0][ar] = av.x; As[ac + 1][ar] = av.y;
        As[ac + 2][ar] = av.z; As[ac + 3][ar] = av.w;
        *(float4*)&Bs[br][bc] = bv;
        __syncthreads();
#pragma unroll
        for (int k = 0; k < 16; k++) {
            float ra[4], rb[4];
#pragma unroll
            for (int i = 0; i < 4; i++) ra[i] = As[k][ty * 4 + i];
#pragma unroll
            for (int j = 0; j < 4; j++) rb[j] = Bs[k][tx * 4 + j];
#pragma unroll
            for (int i = 0; i < 4; i++)
#pragma unroll
                for (int j = 0; j < 4; j++) acc[i][j] += ra[i] * rb[j];
        }
    }
#pragma unroll
    for (int i = 0; i < 4; i++) {
        int m = m0 + ty * 4 + i;
#pragma unroll
        for (int j = 0; j < 4; j++) {
            int nv = nv0 + tx * 4 + j;
            int na = na0 + tx * 4 + j;
            g_gx[(size_t)m * GXN + nv] = acc[i][j] + bg[na];
        }
    }
}

// ---------------- state = (1 - sigmoid(gz)) * tanh(ghh); + tf32 copy ---------
__global__ void k_state(float* __restrict__ out_state) {
    int i = blockIdx.x * blockDim.x + threadIdx.x;
    if (i >= Bx * UX) return;
    int bb = i >> 10, u = i & 1023;
    float gz = g_gx[(size_t)bb * GXN + u];
    float gh = g_gx[(size_t)bb * GXN + UX + u];
    float z = 1.f / (1.f + expf(-gz));
    float st = (1.f - z) * tanhf(gh);
    out_state[i] = st;
    g_statet[i] = f2tf(st);
}

// ============ logits GEMM (mma.sync tf32 + cp.async) =========================
// M=256, N=32000, K=1024. BM=128, BN=128, BK=32. 128 threads, 4 warps 2x2,
// warptile 64x64. grid (250, 2). smem: A 2*18432 @0, B 2*17408 @36864. 71680B.
#define LG_BS_OFF   36864
#define LG_ASTAGE   18432
#define LG_BSTAGE   17408
#define LG_SMEM_BYTES 71680

__global__ void __launch_bounds__(128, 2)
k_logits_tc(const float* __restrict__ Wfc, const float* __restrict__ bfc,
            float* __restrict__ C) {
    extern __shared__ char smraw[];
    uint32_t smu = smem_to_u32(smraw);
    float* smf = (float*)smraw;

    int tid = threadIdx.x;
    int lane = tid & 31, wid = tid >> 5;
    int warp_m = wid & 1, warp_n = wid >> 1;   // 2 x 2 warps
    int g = lane >> 2, tig = lane & 3;
    int m0 = blockIdx.y * 128, n0 = blockIdx.x * 128;

    const float* Ab = g_statet + (size_t)m0 * UX;
    const float* Bb = Wfc + n0;

    int am[8], ak4[8], bk[8], bn4[8];
#pragma unroll
    for (int i = 0; i < 8; i++) {
        int idx = i * 128 + tid;
        am[i] = idx >> 3; ak4[i] = idx & 7;
        bk[i] = idx >> 5; bn4[i] = idx & 31;
    }

#define LG_ISSUE(J) do { \
    int k0 = (J) * 32; int sb = (J) & 1; \
    uint32_t ab = smu + sb * LG_ASTAGE; \
    uint32_t bb = smu + LG_BS_OFF + sb * LG_BSTAGE; \
    _Pragma("unroll") \
    for (int i = 0; i < 8; i++) { \
        cp_async16(ab + (uint32_t)(am[i] * ASTRIDE + ak4[i] * 4) * 4, \
                   Ab + (size_t)am[i] * UX + k0 + ak4[i] * 4); \
        cp_async16(bb + (uint32_t)(bk[i] * BSTRIDE + bn4[i] * 4) * 4, \
                   Bb + (size_t)(k0 + bk[i]) * VOCABX + bn4[i] * 4); \
    } \
    CP_COMMIT(); } while (0)

    float acc[4][8][4] = {};

    LG_ISSUE(0);
    for (int j = 0; j < NKT; j++) {
        CP_WAIT0();
        __syncthreads();
        if (j + 1 < NKT) LG_ISSUE(j + 1);
        const float* Asb = smf + (j & 1) * (LG_ASTAGE / 4);
        const float* Bsb = smf + LG_BS_OFF / 4 + (j & 1) * (LG_BSTAGE / 4);
#pragma unroll
        for (int kk = 0; kk < 32; kk += 8) {
            unsigned afr[4][4], bfr[8][2];
#pragma unroll
            for (int i = 0; i < 4; i++) {
                int row = warp_m * 64 + i * 16 + g;
                afr[i][0] = __float_as_uint(Asb[row * ASTRIDE + kk + tig]);
                afr[i][1] = __float_as_uint(Asb[(row + 8) * ASTRIDE + kk + tig]);
                afr[i][2] = __float_as_uint(Asb[row * ASTRIDE + kk + tig + 4]);
                afr[i][3] = __float_as_uint(Asb[(row + 8) * ASTRIDE + kk + tig + 4]);
            }
#pragma unroll
            for (int jn = 0; jn < 8; jn++) {
                int col = warp_n * 64 + jn * 8 + g;
                bfr[jn][0] = __float_as_uint(Bsb[(kk + tig) * BSTRIDE + col]);
                bfr[jn][1] = __float_as_uint(Bsb[(kk + tig + 4) * BSTRIDE + col]);
            }
#pragma unroll
            for (int i = 0; i < 4; i++)
#pragma unroll
                for (int jn = 0; jn < 8; jn++) mma_tf32(acc[i][jn], afr[i], bfr[jn]);
        }
    }

#pragma unroll
    for (int i = 0; i < 4; i++) {
        int r = m0 + warp_m * 64 + i * 16 + g;
#pragma unroll
        for (int jn = 0; jn < 8; jn++) {
            int n = n0 + warp_n * 64 + jn * 8 + tig * 2;
            float bf0 = bfc[n], bf1 = bfc[n + 1];
            *(float2*)&C[(size_t)r * VOCABX + n] =
                make_float2(acc[i][jn][0] + bf0, acc[i][jn][1] + bf1);
            *(float2*)&C[(size_t)(r + 8) * VOCABX + n] =
                make_float2(acc[i][jn][2] + bf0, acc[i][jn][3] + bf1);
        }
    }
}

// ---------------- launcher ----------------
extern "C" void kernel_launch(void* const* d_in, const int* in_sizes, int n_in,
                              void* d_out, int out_size) {
    const int*   x      = (const int*)d_in[0];
    const float* hidden = (const float*)d_in[1];
    const float* enc    = (const float*)d_in[2];
    const float* E      = (const float*)d_in[3];
    const float* W1     = (const float*)d_in[4];
    const float* b1     = (const float*)d_in[5];
    const float* b2     = (const float*)d_in[7];
    const float* W2     = (const float*)d_in[6];
    const float* V      = (const float*)d_in[8];
    const float* Wx     = (const float*)d_in[10];
    const float* b_gru  = (const float*)d_in[12];
    const float* Wfc    = (const float*)d_in[13];
    const float* bfc    = (const float*)d_in[14];

    float* out        = (float*)d_out;
    float* out_logits = out;
    float* out_state  = out + (size_t)Bx * VOCABX;
    float* out_attn   = out + (size_t)Bx * VOCABX + Bx * UX;

    cudaFuncSetAttribute(k_score_tc, cudaFuncAttributeMaxDynamicSharedMemorySize,
                         SC_SMEM_BYTES);
    cudaFuncSetAttribute(k_logits_tc, cudaFuncAttributeMaxDynamicSharedMemorySize,
                         LG_SMEM_BYTES);

    k_init<<<(Bx * UX + 255) / 256, 256>>>(b1, b2);
    k_round_enc<<<(Bx * Tx * ENCX / 4 + 255) / 256, 256>>>(enc);
    k_transpose_W1<<<dim3(32, 32), dim3(32, 8)>>>(W1);
    k_hw2<<<dim3(16, 4, 8), 256>>>(hidden, W2);
    k_score_tc<<<dim3(UX / 256, Bx), 256, SC_SMEM_BYTES>>>(V);
    k_softmax<<<Bx, 128>>>(x, E, out_attn);
    k_ctx<<<dim3(Bx, ENCX / 256), 256>>>(enc);
    k_gate<<<dim3(GXN / 64, Bx / 64), 256>>>(Wx, b_gru);
    k_state<<<(Bx * UX + 255) / 256, 256>>>(out_state);
    k_logits_tc<<<dim3(VOCABX / 128, Bx / 128), 128, LG_SMEM_BYTES>>>(
        Wfc, bfc, out_logits);
}

// round 8
// speedup vs baseline: 2.5748x; 1.3811x over previous
#include <cuda_runtime.h>
#include <cuda_fp16.h>
#include <cstdint>
#include <math.h>

#define Bx     256
#define Tx     128
#define ENCX   1024
#define UX     1024
#define EMBX   512
#define VOCABX 32000
#define XDIM   1536
#define WXN    3072
#define GXN    2048
#define ASTRIDE 36         // tf32 tile row stride (floats) for logits
#define BSTRIDE 136        // logits B tile: 128 + 8 pad (floats)
#define HSTRW  36          // fp16 tile row stride in 32-bit words (144B rows)

// ---------------- scratch ----------------
__device__ float g_hw2[Bx * UX];
__device__ float g_S[Bx * Tx];
__device__ float g_attn[Bx * Tx];
__device__ float g_xt[Bx * XDIM];
__device__ float g_gx[Bx * GXN];
__device__ float g_statet[Bx * UX];        // tf32-rounded state (logits A)
__device__ __half g_W1th[UX * ENCX];       // W1 transposed (N,K), fp16
__device__ __half g_ench[Bx * Tx * ENCX];  // enc, fp16 (67MB)

__device__ __forceinline__ float f2tf(float f) {
    unsigned u;
    asm("cvt.rna.tf32.f32 %0, %1;" : "=r"(u) : "f"(f));
    return __uint_as_float(u);
}
__device__ __forceinline__ uint32_t smem_to_u32(const void* p) {
    uint32_t a;
    asm("{ .reg .u64 t; cvta.to.shared.u64 t, %1; cvt.u32.u64 %0, t; }"
        : "=r"(a) : "l"(p));
    return a;
}
__device__ __forceinline__ void cp_async16(uint32_t s, const void* g) {
    asm volatile("cp.async.ca.shared.global [%0], [%1], 16;" :: "r"(s), "l"(g));
}
#define CP_COMMIT() asm volatile("cp.async.commit_group;")
#define CP_WAIT0()  asm volatile("cp.async.wait_group 0;")

__device__ __forceinline__ void mma_tf32(float* c, const unsigned* a, const unsigned* b) {
    asm volatile(
        "mma.sync.aligned.m16n8k8.row.col.f32.tf32.tf32.f32 "
        "{%0,%1,%2,%3}, {%4,%5,%6,%7}, {%8,%9}, {%0,%1,%2,%3};"
        : "+f"(c[0]), "+f"(c[1]), "+f"(c[2]), "+f"(c[3])
        : "r"(a[0]), "r"(a[1]), "r"(a[2]), "r"(a[3]), "r"(b[0]), "r"(b[1]));
}
__device__ __forceinline__ void mma_f16(float* c, const unsigned* a, const unsigned* b) {
    asm volatile(
        "mma.sync.aligned.m16n8k16.row.col.f32.f16.f16.f32 "
        "{%0,%1,%2,%3}, {%4,%5,%6,%7}, {%8,%9}, {%0,%1,%2,%3};"
        : "+f"(c[0]), "+f"(c[1]), "+f"(c[2]), "+f"(c[3])
        : "r"(a[0]), "r"(a[1]), "r"(a[2]), "r"(a[3]), "r"(b[0]), "r"(b[1]));
}

// ---------------- init: zero S, g_hw2 = b1 + b2 ----------------
__global__ void k_init(const float* __restrict__ b1, const float* __restrict__ b2) {
    int i = blockIdx.x * blockDim.x + threadIdx.x;
    if (i < Bx * UX) g_hw2[i] = b1[i & 1023] + b2[i & 1023];
    if (i < Bx * Tx) g_S[i] = 0.f;
}

// ---------------- convert enc -> g_ench (fp16 RNE) ----------------
__global__ void k_conv_enc(const float* __restrict__ enc) {
    size_t i = (size_t)(blockIdx.x * blockDim.x + threadIdx.x) * 8;
    size_t n = (size_t)Bx * Tx * ENCX;
    if (i >= n) return;
    float4 v0 = *(const float4*)(enc + i);
    float4 v1 = *(const float4*)(enc + i + 4);
    __half2 h[4];
    h[0] = __floats2half2_rn(v0.x, v0.y);
    h[1] = __floats2half2_rn(v0.z, v0.w);
    h[2] = __floats2half2_rn(v1.x, v1.y);
    h[3] = __floats2half2_rn(v1.z, v1.w);
    *(uint4*)(g_ench + i) = *(const uint4*)h;
}

// ---------------- transpose W1 -> g_W1th (N,K), fp16 ----------------
__global__ void k_transpose_W1(const float* __restrict__ W1) {
    __shared__ float t[32][33];
    int bx = blockIdx.x * 32, by = blockIdx.y * 32;
    int x = threadIdx.x, y0 = threadIdx.y;
#pragma unroll
    for (int i = 0; i < 32; i += 8)
        t[y0 + i][x] = W1[(size_t)(by + y0 + i) * UX + bx + x];
    __syncthreads();
#pragma unroll
    for (int i = 0; i < 32; i += 8)
        g_W1th[(size_t)(bx + y0 + i) * ENCX + by + x] = __float2half_rn(t[x][y0 + i]);
}

// ---------------- hw2 += hidden @ W2 (split-K x8) ----------------
__global__ void k_hw2(const float* __restrict__ hidden, const float* __restrict__ W2) {
    __shared__ float As[16][64];
    __shared__ float Bs[16][64];
    int tid = threadIdx.x;
    int m0 = blockIdx.y * 64, n0 = blockIdx.x * 64;
    int kbase = blockIdx.z * 128;
    int ar = tid >> 2, ac = (tid & 3) << 2;
    int br = tid >> 4, bc = (tid & 15) << 2;
    int ty = tid >> 4, tx = tid & 15;
    float acc[4][4] = {};
    for (int k0 = kbase; k0 < kbase + 128; k0 += 16) {
        float4 av = *(const float4*)&hidden[(size_t)(m0 + ar) * UX + k0 + ac];
        float4 bv = *(const float4*)&W2[(size_t)(k0 + br) * UX + n0 + bc];
        __syncthreads();
        As[ac + 0][ar] = av.x; As[ac + 1][ar] = av.y;
        As[ac + 2][ar] = av.z; As[ac + 3][ar] = av.w;
        *(float4*)&Bs[br][bc] = bv;
        __syncthreads();
#pragma unroll
        for (int k = 0; k < 16; k++) {
            float ra[4], rb[4];
#pragma unroll
            for (int i = 0; i < 4; i++) ra[i] = As[k][ty * 4 + i];
#pragma unroll
            for (int j = 0; j < 4; j++) rb[j] = Bs[k][tx * 4 + j];
#pragma unroll
            for (int i = 0; i < 4; i++)
#pragma unroll
                for (int j = 0; j < 4; j++) acc[i][j] += ra[i] * rb[j];
        }
    }
#pragma unroll
    for (int i = 0; i < 4; i++) {
        int m = m0 + ty * 4 + i;
#pragma unroll
        for (int j = 0; j < 4; j++)
            atomicAdd(&g_hw2[(size_t)m * UX + n0 + tx * 4 + j], acc[i][j]);
    }
}

// ================= score GEMM (mma.sync fp16 m16n8k16 + cp.async) ============
// Block tile 128(m) x 256(n), BK=64 (fp16). 256 threads, 8 warps 2(m) x 4(n),
// warptile 64x64. A [m][k] & B [n][k] fp16 tiles, 144B rows. 2 stages.
// smem: A 2*18432 @0, B 2*36864 @36864, hw2s[256] @110592, Vs[256] @111616,
//       red[128*5] @112640. total 115200.
#define SC_BS_OFF   36864
#define SC_STAGE_A  18432
#define SC_STAGE_B  36864
#define SC_HW2_OFF  110592
#define SC_VS_OFF   111616
#define SC_RED_OFF  112640
#define SC_SMEM_BYTES 115200
#define SC_NKT      16

__global__ void __launch_bounds__(256, 1)
k_score_tc(const float* __restrict__ V) {
    extern __shared__ char smraw[];
    uint32_t smu = smem_to_u32(smraw);
    float* hw2s  = (float*)(smraw + SC_HW2_OFF);
    float* Vs    = (float*)(smraw + SC_VS_OFF);
    float* red   = (float*)(smraw + SC_RED_OFF);

    int tid = threadIdx.x;
    int lane = tid & 31, wid = tid >> 5;
    int warp_m = wid & 1, warp_n = wid >> 1;   // 2 x 4 warps
    int g = lane >> 2, tig = lane & 3;
    int b = blockIdx.y;
    int n0 = blockIdx.x * 256;

    hw2s[tid] = g_hw2[(size_t)b * UX + n0 + tid];
    Vs[tid] = V[n0 + tid];

    const __half* encB = g_ench + (size_t)b * Tx * ENCX;
    const __half* W1tB = g_W1th + (size_t)n0 * ENCX;

    // A: 1024 16B-chunks (4/thread); B: 2048 (8/thread). row = chunks of 8.
    int arw[4], ac16[4], brw[8], bc16[8];
#pragma unroll
    for (int i = 0; i < 4; i++) {
        int idx = i * 256 + tid;
        arw[i] = idx >> 3; ac16[i] = idx & 7;
    }
#pragma unroll
    for (int i = 0; i < 8; i++) {
        int idx = i * 256 + tid;
        brw[i] = idx >> 3; bc16[i] = idx & 7;
    }

#define SC_ISSUE(J) do { \
    int k0 = (J) * 64; int sb = (J) & 1; \
    uint32_t ab = smu + sb * SC_STAGE_A; \
    uint32_t bb = smu + SC_BS_OFF + sb * SC_STAGE_B; \
    _Pragma("unroll") \
    for (int i = 0; i < 4; i++) \
        cp_async16(ab + (uint32_t)(arw[i] * 144 + ac16[i] * 16), \
                   encB + (size_t)arw[i] * ENCX + k0 + ac16[i] * 8); \
    _Pragma("unroll") \
    for (int i = 0; i < 8; i++) \
        cp_async16(bb + (uint32_t)(brw[i] * 144 + bc16[i] * 16), \
                   W1tB + (size_t)brw[i] * ENCX + k0 + bc16[i] * 8); \
    CP_COMMIT(); } while (0)

    float acc[4][8][4] = {};

    SC_ISSUE(0);
    for (int j = 0; j < SC_NKT; j++) {
        CP_WAIT0();
        __syncthreads();
        if (j + 1 < SC_NKT) SC_ISSUE(j + 1);
        const uint32_t* Asb = (const uint32_t*)smraw + (j & 1) * (SC_STAGE_A / 4);
        const uint32_t* Bsb = (const uint32_t*)(smraw + SC_BS_OFF) + (j & 1) * (SC_STAGE_B / 4);
#pragma unroll
        for (int kk2 = 0; kk2 < 32; kk2 += 8) {   // word offset: k16-steps
            unsigned afr[4][4], bfr[8][2];
#pragma unroll
            for (int i = 0; i < 4; i++) {
                int row = warp_m * 64 + i * 16 + g;
                afr[i][0] = Asb[row * HSTRW + kk2 + tig];
                afr[i][1] = Asb[(row + 8) * HSTRW + kk2 + tig];
                afr[i][2] = Asb[row * HSTRW + kk2 + tig + 4];
                afr[i][3] = Asb[(row + 8) * HSTRW + kk2 + tig + 4];
            }
#pragma unroll
            for (int jn = 0; jn < 8; jn++) {
                int col = warp_n * 64 + jn * 8 + g;
                bfr[jn][0] = Bsb[col * HSTRW + kk2 + tig];
                bfr[jn][1] = Bsb[col * HSTRW + kk2 + tig + 4];
            }
#pragma unroll
            for (int i = 0; i < 4; i++)
#pragma unroll
                for (int jn = 0; jn < 8; jn++) mma_f16(acc[i][jn], afr[i], bfr[jn]);
        }
    }

    __syncthreads();
    // epilogue: per-row sum of tanh(acc + hw2)*V
#pragma unroll
    for (int i = 0; i < 4; i++) {
        float s0 = 0.f, s1 = 0.f;
#pragma unroll
        for (int jn = 0; jn < 8; jn++) {
            int nb = warp_n * 64 + jn * 8 + tig * 2;
#pragma unroll
            for (int c = 0; c < 2; c++) {
                int n = nb + c;
                s0 += tanhf(acc[i][jn][c] + hw2s[n]) * Vs[n];
                s1 += tanhf(acc[i][jn][2 + c] + hw2s[n]) * Vs[n];
            }
        }
        s0 += __shfl_xor_sync(0xffffffffu, s0, 1);
        s0 += __shfl_xor_sync(0xffffffffu, s0, 2);
        s1 += __shfl_xor_sync(0xffffffffu, s1, 1);
        s1 += __shfl_xor_sync(0xffffffffu, s1, 2);
        if (tig == 0) {
            int r0 = warp_m * 64 + i * 16 + g;
            red[r0 * 5 + warp_n] = s0;
            red[(r0 + 8) * 5 + warp_n] = s1;
        }
    }
    __syncthreads();
    if (tid < 128) {
        float s = red[tid * 5 + 0] + red[tid * 5 + 1] + red[tid * 5 + 2] + red[tid * 5 + 3];
        atomicAdd(&g_S[b * Tx + tid], s);
    }
}

// ---------------- softmax over T + emb gather ----------------
__global__ void k_softmax(const int* __restrict__ x, const float* __restrict__ E,
                          float* __restrict__ attn_out) {
    int b = blockIdx.x;
    int tid = threadIdx.x;
    __shared__ float sh[128];
    float s = g_S[b * Tx + tid];
    sh[tid] = s;
    __syncthreads();
    for (int off = 64; off; off >>= 1) {
        if (tid < off) sh[tid] = fmaxf(sh[tid], sh[tid + off]);
        __syncthreads();
    }
    float mx = sh[0];
    __syncthreads();
    float e = expf(s - mx);
    sh[tid] = e;
    __syncthreads();
    for (int off = 64; off; off >>= 1) {
        if (tid < off) sh[tid] = sh[tid] + sh[tid + off];
        __syncthreads();
    }
    float a = e / sh[0];
    g_attn[b * Tx + tid] = a;
    attn_out[b * Tx + tid] = a;
    int row = x[b];
    for (int e2 = tid; e2 < EMBX; e2 += 128)
        g_xt[(size_t)b * XDIM + ENCX + e2] = E[(size_t)row * EMBX + e2];
}

// ---------------- context ----------------
__global__ void k_ctx(const float* __restrict__ enc) {
    int b = blockIdx.x;
    int ec = blockIdx.y * 256 + threadIdx.x;
    __shared__ float attn_sh[128];
    if (threadIdx.x < 128) attn_sh[threadIdx.x] = g_attn[b * Tx + threadIdx.x];
    __syncthreads();
    const float* p = enc + (size_t)b * Tx * ENCX + ec;
    float c = 0.f;
#pragma unroll 8
    for (int t = 0; t < Tx; t++) c += attn_sh[t] * p[(size_t)t * ENCX];
    g_xt[(size_t)b * XDIM + ec] = c;
}

// ---------------- gates ----------------
__global__ void k_gate(const float* __restrict__ Wx, const float* __restrict__ bg) {
    __shared__ float As[16][64];
    __shared__ float Bs[16][64];
    int tid = threadIdx.x;
    int m0 = blockIdx.y * 64;
    int nv0 = blockIdx.x * 64;
    int na0 = (nv0 < UX) ? nv0 : nv0 + UX;
    int ar = tid >> 2, ac = (tid & 3) << 2;
    int br = tid >> 4, bc = (tid & 15) << 2;
    int ty = tid >> 4, tx = tid & 15;
    float acc[4][4] = {};
    for (int k0 = 0; k0 < XDIM; k0 += 16) {
        float4 av = *(const float4*)&g_xt[(size_t)(m0 + ar) * XDIM + k0 + ac];
        float4 bv = *(const float4*)&Wx[(size_t)(k0 + br) * WXN + na0 + bc];
        __syncthreads();
        As[ac + 0][ar] = av.x; As[ac + 1][ar] = av.y;
        As[ac + 2][ar] = av.z; As[ac + 3][ar] = av.w;
        *(float4*)&Bs[br][bc] = bv;
        __syncthreads();
#pragma unroll
        for (int k = 0; k < 16; k++) {
            float ra[4], rb[4];
#pragma unroll
            for (int i = 0; i < 4; i++) ra[i] = As[k][ty * 4 + i];
#pragma unroll
            for (int j = 0; j < 4; j++) rb[j] = Bs[k][tx * 4 + j];
#pragma unroll
            for (int i = 0; i < 4; i++)
#pragma unroll
                for (int j = 0; j < 4; j++) acc[i][j] += ra[i] * rb[j];
        }
    }
#pragma unroll
    for (int i = 0; i < 4; i++) {
        int m = m0 + ty * 4 + i;
#pragma unroll
        for (int j = 0; j < 4; j++) {
            int nv = nv0 + tx * 4 + j;
            int na = na0 + tx * 4 + j;
            g_gx[(size_t)m * GXN + nv] = acc[i][j] + bg[na];
        }
    }
}

// ---------------- state = (1 - sigmoid(gz)) * tanh(ghh); + tf32 copy ---------
__global__ void k_state(float* __restrict__ out_state) {
    int i = blockIdx.x * blockDim.x + threadIdx.x;
    if (i >= Bx * UX) return;
    int bb = i >> 10, u = i & 1023;
    float gz = g_gx[(size_t)bb * GXN + u];
    float gh = g_gx[(size_t)bb * GXN + UX + u];
    float z = 1.f / (1.f + expf(-gz));
    float st = (1.f - z) * tanhf(gh);
    out_state[i] = st;
    g_statet[i] = f2tf(st);
}

// ============ logits GEMM (mma.sync tf32 + cp.async, unchanged) ==============
#define LG_BS_OFF   36864
#define LG_ASTAGE   18432
#define LG_BSTAGE   17408
#define LG_SMEM_BYTES 71680
#define LG_NKT      32

__global__ void __launch_bounds__(128, 2)
k_logits_tc(const float* __restrict__ Wfc, const float* __restrict__ bfc,
            float* __restrict__ C) {
    extern __shared__ char smraw[];
    uint32_t smu = smem_to_u32(smraw);
    float* smf = (float*)smraw;

    int tid = threadIdx.x;
    int lane = tid & 31, wid = tid >> 5;
    int warp_m = wid & 1, warp_n = wid >> 1;   // 2 x 2 warps
    int g = lane >> 2, tig = lane & 3;
    int m0 = blockIdx.y * 128, n0 = blockIdx.x * 128;

    const float* Ab = g_statet + (size_t)m0 * UX;
    const float* Bb = Wfc + n0;

    int am[8], ak4[8], bk[8], bn4[8];
#pragma unroll
    for (int i = 0; i < 8; i++) {
        int idx = i * 128 + tid;
        am[i] = idx >> 3; ak4[i] = idx & 7;
        bk[i] = idx >> 5; bn4[i] = idx & 31;
    }

#define LG_ISSUE(J) do { \
    int k0 = (J) * 32; int sb = (J) & 1; \
    uint32_t ab = smu + sb * LG_ASTAGE; \
    uint32_t bb = smu + LG_BS_OFF + sb * LG_BSTAGE; \
    _Pragma("unroll") \
    for (int i = 0; i < 8; i++) { \
        cp_async16(ab + (uint32_t)(am[i] * ASTRIDE + ak4[i] * 4) * 4, \
                   Ab + (size_t)am[i] * UX + k0 + ak4[i] * 4); \
        cp_async16(bb + (uint32_t)(bk[i] * BSTRIDE + bn4[i] * 4) * 4, \
                   Bb + (size_t)(k0 + bk[i]) * VOCABX + bn4[i] * 4); \
    } \
    CP_COMMIT(); } while (0)

    float acc[4][8][4] = {};

    LG_ISSUE(0);
    for (int j = 0; j < LG_NKT; j++) {
        CP_WAIT0();
        __syncthreads();
        if (j + 1 < LG_NKT) LG_ISSUE(j + 1);
        const float* Asb = smf + (j & 1) * (LG_ASTAGE / 4);
        const float* Bsb = smf + LG_BS_OFF / 4 + (j & 1) * (LG_BSTAGE / 4);
#pragma unroll
        for (int kk = 0; kk < 32; kk += 8) {
            unsigned afr[4][4], bfr[8][2];
#pragma unroll
            for (int i = 0; i < 4; i++) {
                int row = warp_m * 64 + i * 16 + g;
                afr[i][0] = __float_as_uint(Asb[row * ASTRIDE + kk + tig]);
                afr[i][1] = __float_as_uint(Asb[(row + 8) * ASTRIDE + kk + tig]);
                afr[i][2] = __float_as_uint(Asb[row * ASTRIDE + kk + tig + 4]);
                afr[i][3] = __float_as_uint(Asb[(row + 8) * ASTRIDE + kk + tig + 4]);
            }
#pragma unroll
            for (int jn = 0; jn < 8; jn++) {
                int col = warp_n * 64 + jn * 8 + g;
                bfr[jn][0] = __float_as_uint(Bsb[(kk + tig) * BSTRIDE + col]);
                bfr[jn][1] = __float_as_uint(Bsb[(kk + tig + 4) * BSTRIDE + col]);
            }
#pragma unroll
            for (int i = 0; i < 4; i++)
#pragma unroll
                for (int jn = 0; jn < 8; jn++) mma_tf32(acc[i][jn], afr[i], bfr[jn]);
        }
    }

#pragma unroll
    for (int i = 0; i < 4; i++) {
        int r = m0 + warp_m * 64 + i * 16 + g;
#pragma unroll
        for (int jn = 0; jn < 8; jn++) {
            int n = n0 + warp_n * 64 + jn * 8 + tig * 2;
            float bf0 = bfc[n], bf1 = bfc[n + 1];
            *(float2*)&C[(size_t)r * VOCABX + n] =
                make_float2(acc[i][jn][0] + bf0, acc[i][jn][1] + bf1);
            *(float2*)&C[(size_t)(r + 8) * VOCABX + n] =
                make_float2(acc[i][jn][2] + bf0, acc[i][jn][3] + bf1);
        }
    }
}

// ---------------- launcher ----------------
extern "C" void kernel_launch(void* const* d_in, const int* in_sizes, int n_in,
                              void* d_out, int out_size) {
    const int*   x      = (const int*)d_in[0];
    const float* hidden = (const float*)d_in[1];
    const float* enc    = (const float*)d_in[2];
    const float* E      = (const float*)d_in[3];
    const float* W1     = (const float*)d_in[4];
    const float* b1     = (const float*)d_in[5];
    const float* W2     = (const float*)d_in[6];
    const float* b2     = (const float*)d_in[7];
    const float* V      = (const float*)d_in[8];
    const float* Wx     = (const float*)d_in[10];
    const float* b_gru  = (const float*)d_in[12];
    const float* Wfc    = (const float*)d_in[13];
    const float* bfc    = (const float*)d_in[14];

    float* out        = (float*)d_out;
    float* out_logits = out;
    float* out_state  = out + (size_t)Bx * VOCABX;
    float* out_attn   = out + (size_t)Bx * VOCABX + Bx * UX;

    cudaFuncSetAttribute(k_score_tc, cudaFuncAttributeMaxDynamicSharedMemorySize,
                         SC_SMEM_BYTES);
    cudaFuncSetAttribute(k_logits_tc, cudaFuncAttributeMaxDynamicSharedMemorySize,
                         LG_SMEM_BYTES);

    k_init<<<(Bx * UX + 255) / 256, 256>>>(b1, b2);
    k_conv_enc<<<(Bx * Tx * ENCX / 8 + 255) / 256, 256>>>(enc);
    k_transpose_W1<<<dim3(32, 32), dim3(32, 8)>>>(W1);
    k_hw2<<<dim3(16, 4, 8), 256>>>(hidden, W2);
    k_score_tc<<<dim3(UX / 256, Bx), 256, SC_SMEM_BYTES>>>(V);
    k_softmax<<<Bx, 128>>>(x, E, out_attn);
    k_ctx<<<dim3(Bx, ENCX / 256), 256>>>(enc);
    k_gate<<<dim3(GXN / 64, Bx / 64), 256>>>(Wx, b_gru);
    k_state<<<(Bx * UX + 255) / 256, 256>>>(out_state);
    k_logits_tc<<<dim3(VOCABX / 128, Bx / 128), 128, LG_SMEM_BYTES>>>(
        Wfc, bfc, out_logits);
}